// round 13
// baseline (speedup 1.0000x reference)
#include <cuda_runtime.h>
#include <cuda_fp16.h>
#include <math.h>
#include <stdint.h>

#define NN_NODE 10000
#define E_NUM   320000
#define FDIM    256
#define NLAYERS 5
#define OC      128
#define KTOT    (NLAYERS*FDIM)   // 1280

// ---------------- scratch ----------------
__device__ float g_dinv[2][NN_NODE];
__device__ int   g_cnt[2][NN_NODE];
__device__ int   g_rowptr[2][NN_NODE + 1];
__device__ int   g_csr_src[2][E_NUM];
__device__ float g_csr_norm[2][E_NUM];
__device__ __align__(16) __half g_feats[2][(size_t)NN_NODE * KTOT];
__device__ __align__(16) __half g_xh[2][(size_t)NN_NODE * FDIM];
__device__ __align__(16) __half g_wt[2][(size_t)NLAYERS * FDIM * FDIM];
__device__ float g_nodemax[2][NLAYERS][NN_NODE];
__device__ float g_atts[2][NLAYERS];
__device__ __align__(16) __half g_weff[2][OC * KTOT];
__device__ __align__(16) __half g_emb[2][(size_t)NN_NODE * OC];

#define MMA_F16(d, a, b) \
  asm volatile("mma.sync.aligned.m16n8k16.row.col.f32.f16.f16.f32 " \
      "{%0,%1,%2,%3}, {%4,%5,%6,%7}, {%8,%9}, {%0,%1,%2,%3};" \
      : "+f"(d[0]), "+f"(d[1]), "+f"(d[2]), "+f"(d[3]) \
      : "r"(a[0]), "r"(a[1]), "r"(a[2]), "r"(a[3]), "r"(b[0]), "r"(b[1]))

__device__ __forceinline__ void cp16(uint32_t d, const void* s, bool p) {
    int sz = p ? 16 : 0;
    asm volatile("cp.async.cg.shared.global [%0], [%1], 16, %2;\n" :: "r"(d), "l"(s), "r"(sz));
}
__device__ __forceinline__ void cp_commit() { asm volatile("cp.async.commit_group;\n"); }
template <int N> __device__ __forceinline__ void cp_wait() {
    asm volatile("cp.async.wait_group %0;\n" :: "n"(N));
}

// ---------------- generic FP16 GEMM (attconv + final), unchanged from R11 ----------------
template <int BIAS, int OUT_HALF, int STREAM_OUT>
__global__ __launch_bounds__(256) void k_gemm_f16(
        int M, int N, int K,
        const __half* __restrict__ A0, const __half* __restrict__ A1, int lda,
        const __half* __restrict__ B0, const __half* __restrict__ B1, int ldb,
        void* __restrict__ C0, void* __restrict__ C1, int ldc,
        const float* __restrict__ bias0, const float* __restrict__ bias1) {
    constexpr int STAGES = 3;
    constexpr int LD32 = 20;
    constexpr int A_ST = 128 * LD32;
    constexpr int B_ST = 128 * LD32;
    extern __shared__ uint32_t smem[];
    uint32_t* As = smem;
    uint32_t* Bs = smem + STAGES * A_ST;

    const int bz = blockIdx.z;
    const __half* A = bz ? A1 : A0;
    const __half* B = bz ? B1 : B0;
    void* Cv = bz ? C1 : C0;
    const float* bias = bz ? bias1 : bias0;

    const int tid = threadIdx.x;
    const int wid = tid >> 5;
    const int lane = tid & 31;
    const int g = lane >> 2, t = lane & 3;
    const int wm = wid >> 1, wn = wid & 1;
    const int i0 = blockIdx.y * 128, j0 = blockIdx.x * 128;

    const int ar = tid >> 1, akc = (tid & 1) * 16;

    const bool a_ok = (i0 + ar < M);
    const __half* a_src = A + (size_t)(a_ok ? i0 + ar : M - 1) * lda + akc;
    const bool b_ok = (j0 + ar < N);
    const __half* b_src = B + (size_t)(b_ok ? j0 + ar : N - 1) * ldb + akc;

    uint32_t sa_base = (uint32_t)__cvta_generic_to_shared(&As[ar * LD32 + akc / 2]);
    uint32_t sb_base = (uint32_t)__cvta_generic_to_shared(&Bs[ar * LD32 + akc / 2]);

    auto issue = [&](int s, int k0) {
        uint32_t da = sa_base + s * (A_ST * 4);
        const __half* pa = a_src + k0;
        cp16(da,      pa,     a_ok);
        cp16(da + 16, pa + 8, a_ok);
        uint32_t db = sb_base + s * (B_ST * 4);
        const __half* pb = b_src + k0;
        cp16(db,      pb,     b_ok);
        cp16(db + 16, pb + 8, b_ok);
        cp_commit();
    };

    float acc[2][8][4];
    #pragma unroll
    for (int mt = 0; mt < 2; mt++)
        #pragma unroll
        for (int nt = 0; nt < 8; nt++)
            #pragma unroll
            for (int q = 0; q < 4; q++) acc[mt][nt][q] = 0.0f;

    auto compute = [&](int s) {
        const uint32_t* Ab = As + s * A_ST;
        const uint32_t* Bb = Bs + s * B_ST;
        #pragma unroll
        for (int c = 0; c < 2; c++) {
            const int base = c * 8;
            uint32_t af[2][4];
            #pragma unroll
            for (int mt = 0; mt < 2; mt++) {
                int r = wm * 32 + mt * 16;
                af[mt][0] = Ab[(r + g) * LD32 + base + t];
                af[mt][1] = Ab[(r + g + 8) * LD32 + base + t];
                af[mt][2] = Ab[(r + g) * LD32 + base + t + 4];
                af[mt][3] = Ab[(r + g + 8) * LD32 + base + t + 4];
            }
            uint32_t bf[8][2];
            #pragma unroll
            for (int nt = 0; nt < 8; nt++) {
                int n = wn * 64 + nt * 8 + g;
                bf[nt][0] = Bb[n * LD32 + base + t];
                bf[nt][1] = Bb[n * LD32 + base + t + 4];
            }
            #pragma unroll
            for (int mt = 0; mt < 2; mt++)
                #pragma unroll
                for (int nt = 0; nt < 8; nt++)
                    MMA_F16(acc[mt][nt], af[mt], bf[nt]);
        }
    };

    const int ktiles = K / 32;
    issue(0, 0);
    if (ktiles > 1) issue(1, 32);
    for (int i = 0; i < ktiles; i++) {
        if (i < ktiles - 1) cp_wait<STAGES - 2>(); else cp_wait<0>();
        __syncthreads();
        int pf = i + STAGES - 1;
        if (pf < ktiles) issue(pf % STAGES, pf * 32);
        compute(i % STAGES);
    }

    #pragma unroll
    for (int mt = 0; mt < 2; mt++) {
        int r0 = i0 + wm * 32 + mt * 16 + g;
        #pragma unroll
        for (int nt = 0; nt < 8; nt++) {
            int c = j0 + wn * 64 + nt * 8 + 2 * t;
            if (c >= N) continue;
            float bx0 = 0.f, bx1 = 0.f;
            if (BIAS) { bx0 = bias[c]; bx1 = bias[c + 1]; }
            float v00 = acc[mt][nt][0] + bx0, v01 = acc[mt][nt][1] + bx1;
            float v10 = acc[mt][nt][2] + bx0, v11 = acc[mt][nt][3] + bx1;
            if (OUT_HALF) {
                __half* Ch = (__half*)Cv;
                __half2 h0 = __float22half2_rn(make_float2(v00, v01));
                __half2 h1 = __float22half2_rn(make_float2(v10, v11));
                if (r0 < M)     *(__half2*)(Ch + (size_t)r0 * ldc + c) = h0;
                if (r0 + 8 < M) *(__half2*)(Ch + (size_t)(r0 + 8) * ldc + c) = h1;
            } else {
                float* Cf = (float*)Cv;
                float2 p0 = make_float2(v00, v01);
                float2 p1 = make_float2(v10, v11);
                if (STREAM_OUT) {
                    if (r0 < M)     __stcs((float2*)(Cf + (size_t)r0 * ldc + c), p0);
                    if (r0 + 8 < M) __stcs((float2*)(Cf + (size_t)(r0 + 8) * ldc + c), p1);
                } else {
                    if (r0 < M)     *(float2*)(Cf + (size_t)r0 * ldc + c) = p0;
                    if (r0 + 8 < M) *(float2*)(Cf + (size_t)(r0 + 8) * ldc + c) = p1;
                }
            }
        }
    }
}

// ---------------- fused layer: t = agg(in) gathered to smem, feats_layer = relu(t@W + b), nodemax ----------------
// 64 nodes per block, 256 threads. smem: t[64][264h] + B 3 stages + nmax[64].
__global__ __launch_bounds__(256) void k_fused(
        const __half* __restrict__ in, int ldin,
        const __half* __restrict__ Wt,
        const float* __restrict__ bias,
        __half* __restrict__ feats, int b, int layer) {
    constexpr int ROWS = 64;
    constexpr int LDT = 132;            // u32 per t row (256 halves + 8 pad)
    constexpr int LDB = 20;             // u32 per B row (32 halves + 8 pad)
    constexpr int B_ST = 128 * LDB;
    extern __shared__ uint32_t sm[];
    uint32_t* ts = sm;                        // 64*132 u32
    uint32_t* Bs = sm + ROWS * LDT;           // 3*B_ST u32
    float* nmax_s = (float*)(Bs + 3 * B_ST);  // 64 floats

    const int tid = threadIdx.x;
    const int wid = tid >> 5, lane = tid & 31;
    const int i0 = blockIdx.x * ROWS;

    // B loader mapping (identical to validated GEMM)
    const int ar = tid >> 1, akc = (tid & 1) * 16;
    uint32_t sb_base = (uint32_t)__cvta_generic_to_shared(&Bs[ar * LDB + akc / 2]);
    const __half* b_row = Wt + (size_t)ar * 256 + akc;
    auto issueB = [&](int stage, int n0, int kt) {
        uint32_t db = sb_base + stage * (B_ST * 4);
        const __half* pb = b_row + (size_t)n0 * 256 + kt * 32;
        cp16(db, pb, true);
        cp16(db + 16, pb + 8, true);
        cp_commit();
    };
    issueB(0, 0, 0);                 // prefetch pass-0 tiles under the gather
    issueB(1, 0, 1);

    if (tid < ROWS) nmax_s[tid] = 0.f;

    // ---- gather phase: 8 warps x 8 nodes; lane holds 8 halves (uint4) ----
    for (int nn = 0; nn < 8; nn++) {
        int r = wid * 8 + nn;
        int v = i0 + r;
        float acc[8];
        #pragma unroll
        for (int q = 0; q < 8; q++) acc[q] = 0.f;
        if (v < NN_NODE) {
            float dv = g_dinv[b][v];
            float sw = dv * dv;
            uint4 raw = *((const uint4*)(in + (size_t)v * ldin) + lane);
            {
                float2 c0 = __half22float2(*(__half2*)&raw.x);
                float2 c1 = __half22float2(*(__half2*)&raw.y);
                float2 c2 = __half22float2(*(__half2*)&raw.z);
                float2 c3 = __half22float2(*(__half2*)&raw.w);
                acc[0] = sw * c0.x; acc[1] = sw * c0.y; acc[2] = sw * c1.x; acc[3] = sw * c1.y;
                acc[4] = sw * c2.x; acc[5] = sw * c2.y; acc[6] = sw * c3.x; acc[7] = sw * c3.y;
            }
            int e = g_rowptr[b][v];
            int e2 = g_rowptr[b][v + 1];
            const int*   srcs  = g_csr_src[b];
            const float* norms = g_csr_norm[b];
            auto fma8 = [&](float n, uint4 rr) {
                float2 c0 = __half22float2(*(__half2*)&rr.x);
                float2 c1 = __half22float2(*(__half2*)&rr.y);
                float2 c2 = __half22float2(*(__half2*)&rr.z);
                float2 c3 = __half22float2(*(__half2*)&rr.w);
                acc[0] += n * c0.x; acc[1] += n * c0.y; acc[2] += n * c1.x; acc[3] += n * c1.y;
                acc[4] += n * c2.x; acc[5] += n * c2.y; acc[6] += n * c3.x; acc[7] += n * c3.y;
            };
            for (; e + 4 <= e2; e += 4) {
                uint4 r0 = *((const uint4*)(in + (size_t)srcs[e + 0] * ldin) + lane);
                uint4 r1 = *((const uint4*)(in + (size_t)srcs[e + 1] * ldin) + lane);
                uint4 r2 = *((const uint4*)(in + (size_t)srcs[e + 2] * ldin) + lane);
                uint4 r3 = *((const uint4*)(in + (size_t)srcs[e + 3] * ldin) + lane);
                fma8(norms[e + 0], r0); fma8(norms[e + 1], r1);
                fma8(norms[e + 2], r2); fma8(norms[e + 3], r3);
            }
            for (; e < e2; e++) fma8(norms[e], *((const uint4*)(in + (size_t)srcs[e] * ldin) + lane));
        }
        __half2 p0 = __float22half2_rn(make_float2(acc[0], acc[1]));
        __half2 p1 = __float22half2_rn(make_float2(acc[2], acc[3]));
        __half2 p2 = __float22half2_rn(make_float2(acc[4], acc[5]));
        __half2 p3 = __float22half2_rn(make_float2(acc[6], acc[7]));
        uint4 outv = make_uint4(*(uint32_t*)&p0, *(uint32_t*)&p1, *(uint32_t*)&p2, *(uint32_t*)&p3);
        *(uint4*)&ts[r * LDT + lane * 4] = outv;
    }
    __syncthreads();

    // ---- GEMM phases: warp tile 16 rows x 64 cols; two N-passes ----
    const int g = lane >> 2, t4 = lane & 3;
    const int wm = wid >> 1, wn = wid & 1;

    for (int pass = 0; pass < 2; pass++) {
        const int n0 = pass * 128;
        if (pass == 1) {
            __syncthreads();             // stages of pass 0 fully consumed
            issueB(0, 128, 0);
            issueB(1, 128, 1);
        }
        float acc[8][4];
        #pragma unroll
        for (int nt = 0; nt < 8; nt++)
            #pragma unroll
            for (int q = 0; q < 4; q++) acc[nt][q] = 0.f;

        for (int kt = 0; kt < 8; kt++) {
            // group accounting: issued newest = kt+1 at wait time -> wait<1> leaves only it pending.
            if (kt < 7) cp_wait<1>(); else cp_wait<0>();
            __syncthreads();
            if (kt + 2 < 8) issueB((kt + 2) % 3, n0, kt + 2);
            const uint32_t* Bb = Bs + (kt % 3) * B_ST;
            #pragma unroll
            for (int c = 0; c < 2; c++) {
                const int base = c * 8;
                uint32_t af[4];
                const int rr = wm * 16;
                af[0] = ts[(rr + g) * LDT + kt * 16 + base + t4];
                af[1] = ts[(rr + g + 8) * LDT + kt * 16 + base + t4];
                af[2] = ts[(rr + g) * LDT + kt * 16 + base + t4 + 4];
                af[3] = ts[(rr + g + 8) * LDT + kt * 16 + base + t4 + 4];
                #pragma unroll
                for (int nt = 0; nt < 8; nt++) {
                    int n = wn * 64 + nt * 8 + g;
                    uint32_t bf[2];
                    bf[0] = Bb[n * LDB + base + t4];
                    bf[1] = Bb[n * LDB + base + t4 + 4];
                    MMA_F16(acc[nt], af, bf);
                }
            }
        }

        // epilogue: relu(acc + bias), half store, per-row max
        const int r0 = i0 + wm * 16 + g;
        float lm0 = 0.f, lm1 = 0.f;
        #pragma unroll
        for (int nt = 0; nt < 8; nt++) {
            int c = n0 + wn * 64 + nt * 8 + 2 * t4;
            float bx0 = bias[c], bx1 = bias[c + 1];
            float v00 = fmaxf(acc[nt][0] + bx0, 0.f);
            float v01 = fmaxf(acc[nt][1] + bx1, 0.f);
            float v10 = fmaxf(acc[nt][2] + bx0, 0.f);
            float v11 = fmaxf(acc[nt][3] + bx1, 0.f);
            lm0 = fmaxf(lm0, fmaxf(v00, v01));
            lm1 = fmaxf(lm1, fmaxf(v10, v11));
            __half2 h0 = __float22half2_rn(make_float2(v00, v01));
            __half2 h1 = __float22half2_rn(make_float2(v10, v11));
            if (r0 < NN_NODE)
                *(__half2*)&feats[(size_t)r0 * KTOT + layer * FDIM + c] = h0;
            if (r0 + 8 < NN_NODE)
                *(__half2*)&feats[(size_t)(r0 + 8) * KTOT + layer * FDIM + c] = h1;
        }
        atomicMax((int*)&nmax_s[wm * 16 + g],     __float_as_int(lm0));
        atomicMax((int*)&nmax_s[wm * 16 + g + 8], __float_as_int(lm1));
    }
    __syncthreads();
    if (tid < ROWS && i0 + tid < NN_NODE)
        g_nodemax[b][layer][i0 + tid] = nmax_s[tid];
}

// ---------------- streams/attrs ----------------
#define SMEM_FUSED ((64 * 132 + 3 * 128 * 20) * 4 + 256)
struct HxRes {
    cudaStream_t s0, s1;
    cudaEvent_t ev_fork, ev_j0, ev_j1;
    HxRes() {
        cudaStreamCreateWithFlags(&s0, cudaStreamNonBlocking);
        cudaStreamCreateWithFlags(&s1, cudaStreamNonBlocking);
        cudaEventCreateWithFlags(&ev_fork, cudaEventDisableTiming);
        cudaEventCreateWithFlags(&ev_j0, cudaEventDisableTiming);
        cudaEventCreateWithFlags(&ev_j1, cudaEventDisableTiming);
        cudaFuncSetAttribute((const void*)k_fused, cudaFuncAttributeMaxDynamicSharedMemorySize, SMEM_FUSED);
        cudaFuncSetAttribute((const void*)k_gemm_f16<1,1,0>, cudaFuncAttributeMaxDynamicSharedMemorySize, 65536);
        cudaFuncSetAttribute((const void*)k_gemm_f16<0,0,1>, cudaFuncAttributeMaxDynamicSharedMemorySize, 65536);
    }
};
static HxRes g_hx;

// ---------------- per-branch prep ----------------
__global__ void k_halfcpy(const float* __restrict__ in, __half* __restrict__ out, int n4) {
    int i = blockIdx.x * blockDim.x + threadIdx.x;
    if (i < n4) {
        float4 v = ((const float4*)in)[i];
        __half2 h0 = __float22half2_rn(make_float2(v.x, v.y));
        __half2 h1 = __float22half2_rn(make_float2(v.z, v.w));
        ((uint2*)out)[i] = make_uint2(*(uint32_t*)&h0, *(uint32_t*)&h1);
    }
}

__global__ void k_halfT(const float* __restrict__ in, __half* __restrict__ out, int total) {
    int idx = blockIdx.x * blockDim.x + threadIdx.x;
    if (idx < total) {
        int l = idx >> 16;
        int rem = idx & 65535;
        int k = rem >> 8, n = rem & 255;
        out[(size_t)l * 65536 + n * 256 + k] = __float2half(in[idx]);
    }
}

__global__ void k_init1(int b) {
    int i = blockIdx.x * blockDim.x + threadIdx.x;
    if (i < NN_NODE) { g_dinv[b][i] = 1.0f; g_cnt[b][i] = 0; }
}

__global__ void k_deg1(const int* __restrict__ edges, const float* __restrict__ w, int b) {
    int e = blockIdx.x * blockDim.x + threadIdx.x;
    if (e < E_NUM) {
        int dst = edges[E_NUM + e];
        atomicAdd(&g_dinv[b][dst], w[e]);
        atomicAdd(&g_cnt[b][dst], 1);
    }
}

__global__ void k_scan1(int b) {
    __shared__ int wsum[32];
    __shared__ int chunk_base;
    int tid = threadIdx.x, lane = tid & 31, w = tid >> 5;
    if (tid == 0) chunk_base = 0;
    __syncthreads();
    for (int c0 = 0; c0 < NN_NODE; c0 += 1024) {
        int idx = c0 + tid;
        int v = (idx < NN_NODE) ? g_cnt[b][idx] : 0;
        if (idx < NN_NODE) g_dinv[b][idx] = rsqrtf(g_dinv[b][idx]);
        int sc = v;
        #pragma unroll
        for (int off = 1; off < 32; off <<= 1) {
            int u = __shfl_up_sync(0xffffffffu, sc, off);
            if (lane >= off) sc += u;
        }
        if (lane == 31) wsum[w] = sc;
        __syncthreads();
        if (w == 0) {
            int tv = wsum[lane];
            #pragma unroll
            for (int off = 1; off < 32; off <<= 1) {
                int u = __shfl_up_sync(0xffffffffu, tv, off);
                if (lane >= off) tv += u;
            }
            wsum[lane] = tv;
        }
        __syncthreads();
        int total = wsum[31];
        int excl = chunk_base + (w ? wsum[w - 1] : 0) + sc - v;
        if (idx < NN_NODE) { g_rowptr[b][idx] = excl; g_cnt[b][idx] = 0; }
        __syncthreads();
        if (tid == 0) chunk_base += total;
        __syncthreads();
    }
    if (tid == 0) g_rowptr[b][NN_NODE] = chunk_base;
}

__global__ void k_fill1(const int* __restrict__ edges, const float* __restrict__ w, int b) {
    int e = blockIdx.x * blockDim.x + threadIdx.x;
    if (e < E_NUM) {
        int s = edges[e];
        int d = edges[E_NUM + e];
        int pos = g_rowptr[b][d] + atomicAdd(&g_cnt[b][d], 1);
        g_csr_src[b][pos] = s;
        g_csr_norm[b][pos] = g_dinv[b][s] * w[e] * g_dinv[b][d];
    }
}

// ---------------- attention FC (node-max reduce) + effective conv weights ----------------
__global__ void k_attfc2(const float* __restrict__ fc1w, const float* __restrict__ fc1b,
                         const float* __restrict__ fc2w, const float* __restrict__ fc2b, int b) {
    __shared__ float red[256];
    __shared__ float amax_s[NLAYERS];
    int tid = threadIdx.x;
    for (int c = 0; c < NLAYERS; c++) {
        float m = 0.f;
        for (int i = tid; i < NN_NODE; i += 256) m = fmaxf(m, g_nodemax[b][c][i]);
        red[tid] = m;
        __syncthreads();
        for (int o = 128; o > 0; o >>= 1) {
            if (tid < o) red[tid] = fmaxf(red[tid], red[tid + o]);
            __syncthreads();
        }
        if (tid == 0) amax_s[c] = red[0];
        __syncthreads();
    }
    if (tid == 0) {
        float t[5 * NLAYERS];
        for (int j = 0; j < 5 * NLAYERS; j++) {
            float s = fc1b[j];
            for (int c = 0; c < NLAYERS; c++) s += fc1w[j * NLAYERS + c] * amax_s[c];
            t[j] = fmaxf(s, 0.f);
        }
        for (int c = 0; c < NLAYERS; c++) {
            float s = fc2b[c];
            for (int j = 0; j < 5 * NLAYERS; j++) s += fc2w[c * (5 * NLAYERS) + j] * t[j];
            g_atts[b][c] = 1.0f / (1.0f + expf(-s));
        }
    }
}

__global__ void k_weff(const float* __restrict__ cw, int b) {
    int idx = blockIdx.x * blockDim.x + threadIdx.x;
    if (idx < OC * KTOT) {
        int c = (idx % KTOT) >> 8;
        g_weff[b][idx] = __float2half(cw[idx] * g_atts[b][c]);
    }
}

// ---------------- launch ----------------
extern "C" void kernel_launch(void* const* d_in, const int* in_sizes, int n_in,
                              void* d_out, int out_size) {
    const float* x_m    = (const float*)d_in[0];
    const float* x_d    = (const float*)d_in[1];
    const float* w_m    = (const float*)d_in[2];
    const float* w_d    = (const float*)d_in[3];
    const float* Wx     = (const float*)d_in[4];
    const float* bx     = (const float*)d_in[5];
    const float* Wy     = (const float*)d_in[6];
    const float* by     = (const float*)d_in[7];
    const float* fc1x_w = (const float*)d_in[8];
    const float* fc1x_b = (const float*)d_in[9];
    const float* fc2x_w = (const float*)d_in[10];
    const float* fc2x_b = (const float*)d_in[11];
    const float* fc1y_w = (const float*)d_in[12];
    const float* fc1y_b = (const float*)d_in[13];
    const float* fc2y_w = (const float*)d_in[14];
    const float* fc2y_b = (const float*)d_in[15];
    const float* cnnx_w = (const float*)d_in[16];
    const float* cnnx_b = (const float*)d_in[17];
    const float* cnny_w = (const float*)d_in[18];
    const float* cnny_b = (const float*)d_in[19];
    const int*   edges_m = (const int*)d_in[20];
    const int*   edges_d = (const int*)d_in[21];
    float* out = (float*)d_out;

    __half *p_feats, *p_weff, *p_emb, *p_xh, *p_wt;
    cudaGetSymbolAddress((void**)&p_feats, g_feats);
    cudaGetSymbolAddress((void**)&p_weff,  g_weff);
    cudaGetSymbolAddress((void**)&p_emb,   g_emb);
    cudaGetSymbolAddress((void**)&p_xh,    g_xh);
    cudaGetSymbolAddress((void**)&p_wt,    g_wt);

    __half* emb0 = p_emb;
    __half* emb1 = p_emb + (size_t)NN_NODE * OC;

    const int MT = (NN_NODE + 127) / 128;   // 79
    const int FB = (NN_NODE + 63) / 64;     // 157
    const int SM_F16 = 3 * (128 * 20 + 128 * 20) * 4;  // 61440

    cudaEventRecord(g_hx.ev_fork, 0);
    cudaStreamWaitEvent(g_hx.s0, g_hx.ev_fork, 0);
    cudaStreamWaitEvent(g_hx.s1, g_hx.ev_fork, 0);

    for (int b = 0; b < 2; b++) {
        cudaStream_t st = b ? g_hx.s1 : g_hx.s0;
        const int*   edges = b ? edges_d : edges_m;
        const float* w     = b ? w_d : w_m;
        const float* W     = b ? Wy : Wx;
        const float* bias  = b ? by : bx;
        const float* x0    = b ? x_d : x_m;
        const float* fc1w  = b ? fc1y_w : fc1x_w;
        const float* fc1b  = b ? fc1y_b : fc1x_b;
        const float* fc2w  = b ? fc2y_w : fc2x_w;
        const float* fc2b  = b ? fc2y_b : fc2x_b;
        const float* cw    = b ? cnny_w : cnnx_w;
        const float* cb    = b ? cnny_b : cnnx_b;
        __half* featsB = p_feats + (size_t)b * NN_NODE * KTOT;
        __half* xhB    = p_xh    + (size_t)b * NN_NODE * FDIM;
        __half* wtB    = p_wt    + (size_t)b * NLAYERS * FDIM * FDIM;
        __half* weffB  = p_weff  + (size_t)b * OC * KTOT;
        __half* embB   = b ? emb1 : emb0;

        // conversions + per-branch CSR, all on this branch's stream (fully independent)
        k_halfcpy<<<(NN_NODE * FDIM / 4 + 255) / 256, 256, 0, st>>>(x0, xhB, NN_NODE * FDIM / 4);
        k_halfT<<<(NLAYERS * FDIM * FDIM + 255) / 256, 256, 0, st>>>(W, wtB, NLAYERS * FDIM * FDIM);
        k_init1<<<(NN_NODE + 255) / 256, 256, 0, st>>>(b);
        k_deg1<<<E_NUM / 256, 256, 0, st>>>(edges, w, b);
        k_scan1<<<1, 1024, 0, st>>>(b);
        k_fill1<<<E_NUM / 256, 256, 0, st>>>(edges, w, b);

        // fused layers
        for (int i = 0; i < NLAYERS; i++) {
            const __half* in = i ? featsB + (size_t)(i - 1) * FDIM : xhB;
            int ldin = i ? KTOT : FDIM;
            k_fused<<<FB, 256, SMEM_FUSED, st>>>(
                in, ldin, wtB + (size_t)i * FDIM * FDIM, bias + (size_t)i * FDIM,
                featsB, b, i);
        }

        // per-branch tail
        k_attfc2<<<1, 256, 0, st>>>(fc1w, fc1b, fc2w, fc2b, b);
        k_weff<<<(OC * KTOT + 255) / 256, 256, 0, st>>>(cw, b);
        k_gemm_f16<1, 1, 0><<<dim3(1, MT, 1), 256, SM_F16, st>>>(
            NN_NODE, OC, KTOT,
            featsB, featsB, KTOT,
            weffB, weffB, KTOT,
            embB, embB, OC,
            cb, cb);
    }

    cudaEventRecord(g_hx.ev_j0, g_hx.s0);
    cudaEventRecord(g_hx.ev_j1, g_hx.s1);
    cudaStreamWaitEvent(0, g_hx.ev_j0, 0);
    cudaStreamWaitEvent(0, g_hx.ev_j1, 0);

    k_gemm_f16<0, 0, 1><<<dim3(MT, MT, 1), 256, SM_F16>>>(
        NN_NODE, NN_NODE, OC,
        emb0, emb0, OC,
        emb1, emb1, OC,
        out, out, NN_NODE,
        nullptr, nullptr);
}

// round 14
// speedup vs baseline: 1.1654x; 1.1654x over previous
#include <cuda_runtime.h>
#include <cuda_fp16.h>
#include <math.h>
#include <stdint.h>

#define NN_NODE 10000
#define E_NUM   320000
#define FDIM    256
#define NLAYERS 5
#define OC      128
#define KTOT    (NLAYERS*FDIM)   // 1280

// ---------------- scratch ----------------
__device__ float g_dinv[2][NN_NODE];
__device__ int   g_cnt[2][NN_NODE];
__device__ int   g_rowptr[2][NN_NODE + 1];
__device__ int   g_csr_src[2][E_NUM];
__device__ float g_csr_norm[2][E_NUM];
__device__ __align__(16) __half g_feats[2][(size_t)NN_NODE * KTOT];
__device__ __align__(16) __half g_h1[2][(size_t)NN_NODE * FDIM];
__device__ __align__(16) __half g_xh[2][(size_t)NN_NODE * FDIM];
__device__ __align__(16) __half g_wt[2][(size_t)NLAYERS * FDIM * FDIM];
__device__ float g_nodemax[2][NLAYERS][NN_NODE];
__device__ float g_atts[2][NLAYERS];
__device__ __align__(16) __half g_weff[2][OC * KTOT];
__device__ __align__(16) __half g_emb[2][(size_t)NN_NODE * OC];

// ---------------- FP16 cp.async GEMM 128x128x32, 3-stage, optional z-batch ----------------
#define MMA_F16(d, a, b) \
  asm volatile("mma.sync.aligned.m16n8k16.row.col.f32.f16.f16.f32 " \
      "{%0,%1,%2,%3}, {%4,%5,%6,%7}, {%8,%9}, {%0,%1,%2,%3};" \
      : "+f"(d[0]), "+f"(d[1]), "+f"(d[2]), "+f"(d[3]) \
      : "r"(a[0]), "r"(a[1]), "r"(a[2]), "r"(a[3]), "r"(b[0]), "r"(b[1]))

__device__ __forceinline__ void cp16(uint32_t d, const void* s, bool p) {
    int sz = p ? 16 : 0;
    asm volatile("cp.async.cg.shared.global [%0], [%1], 16, %2;\n" :: "r"(d), "l"(s), "r"(sz));
}
__device__ __forceinline__ void cp_commit() { asm volatile("cp.async.commit_group;\n"); }
template <int N> __device__ __forceinline__ void cp_wait() {
    asm volatile("cp.async.wait_group %0;\n" :: "n"(N));
}

template <int BIAS, int OUT_HALF, int STREAM_OUT>
__global__ __launch_bounds__(256) void k_gemm_f16(
        int M, int N, int K,
        const __half* __restrict__ A0, const __half* __restrict__ A1, int lda,
        const __half* __restrict__ B0, const __half* __restrict__ B1, int ldb,
        void* __restrict__ C0, void* __restrict__ C1, int ldc,
        const float* __restrict__ bias0, const float* __restrict__ bias1) {
    constexpr int STAGES = 3;
    constexpr int LD32 = 20;
    constexpr int A_ST = 128 * LD32;
    constexpr int B_ST = 128 * LD32;
    extern __shared__ uint32_t smem[];
    uint32_t* As = smem;
    uint32_t* Bs = smem + STAGES * A_ST;

    const int bz = blockIdx.z;
    const __half* A = bz ? A1 : A0;
    const __half* B = bz ? B1 : B0;
    void* Cv = bz ? C1 : C0;
    const float* bias = bz ? bias1 : bias0;

    const int tid = threadIdx.x;
    const int wid = tid >> 5;
    const int lane = tid & 31;
    const int g = lane >> 2, t = lane & 3;
    const int wm = wid >> 1, wn = wid & 1;
    const int i0 = blockIdx.y * 128, j0 = blockIdx.x * 128;

    const int ar = tid >> 1, akc = (tid & 1) * 16;

    const bool a_ok = (i0 + ar < M);
    const __half* a_src = A + (size_t)(a_ok ? i0 + ar : M - 1) * lda + akc;
    const bool b_ok = (j0 + ar < N);
    const __half* b_src = B + (size_t)(b_ok ? j0 + ar : N - 1) * ldb + akc;

    uint32_t sa_base = (uint32_t)__cvta_generic_to_shared(&As[ar * LD32 + akc / 2]);
    uint32_t sb_base = (uint32_t)__cvta_generic_to_shared(&Bs[ar * LD32 + akc / 2]);

    auto issue = [&](int s, int k0) {
        uint32_t da = sa_base + s * (A_ST * 4);
        const __half* pa = a_src + k0;
        cp16(da,      pa,     a_ok);
        cp16(da + 16, pa + 8, a_ok);
        uint32_t db = sb_base + s * (B_ST * 4);
        const __half* pb = b_src + k0;
        cp16(db,      pb,     b_ok);
        cp16(db + 16, pb + 8, b_ok);
        cp_commit();
    };

    float acc[2][8][4];
    #pragma unroll
    for (int mt = 0; mt < 2; mt++)
        #pragma unroll
        for (int nt = 0; nt < 8; nt++)
            #pragma unroll
            for (int q = 0; q < 4; q++) acc[mt][nt][q] = 0.0f;

    auto compute = [&](int s) {
        const uint32_t* Ab = As + s * A_ST;
        const uint32_t* Bb = Bs + s * B_ST;
        #pragma unroll
        for (int c = 0; c < 2; c++) {
            const int base = c * 8;
            uint32_t af[2][4];
            #pragma unroll
            for (int mt = 0; mt < 2; mt++) {
                int r = wm * 32 + mt * 16;
                af[mt][0] = Ab[(r + g) * LD32 + base + t];
                af[mt][1] = Ab[(r + g + 8) * LD32 + base + t];
                af[mt][2] = Ab[(r + g) * LD32 + base + t + 4];
                af[mt][3] = Ab[(r + g + 8) * LD32 + base + t + 4];
            }
            uint32_t bf[8][2];
            #pragma unroll
            for (int nt = 0; nt < 8; nt++) {
                int n = wn * 64 + nt * 8 + g;
                bf[nt][0] = Bb[n * LD32 + base + t];
                bf[nt][1] = Bb[n * LD32 + base + t + 4];
            }
            #pragma unroll
            for (int mt = 0; mt < 2; mt++)
                #pragma unroll
                for (int nt = 0; nt < 8; nt++)
                    MMA_F16(acc[mt][nt], af[mt], bf[nt]);
        }
    };

    const int ktiles = K / 32;
    issue(0, 0);
    if (ktiles > 1) issue(1, 32);
    for (int i = 0; i < ktiles; i++) {
        if (i < ktiles - 1) cp_wait<STAGES - 2>(); else cp_wait<0>();
        __syncthreads();
        int pf = i + STAGES - 1;
        if (pf < ktiles) issue(pf % STAGES, pf * 32);
        compute(i % STAGES);
    }

    #pragma unroll
    for (int mt = 0; mt < 2; mt++) {
        int r0 = i0 + wm * 32 + mt * 16 + g;
        #pragma unroll
        for (int nt = 0; nt < 8; nt++) {
            int c = j0 + wn * 64 + nt * 8 + 2 * t;
            if (c >= N) continue;
            float bx0 = 0.f, bx1 = 0.f;
            if (BIAS) { bx0 = bias[c]; bx1 = bias[c + 1]; }
            float v00 = acc[mt][nt][0] + bx0, v01 = acc[mt][nt][1] + bx1;
            float v10 = acc[mt][nt][2] + bx0, v11 = acc[mt][nt][3] + bx1;
            if (OUT_HALF) {
                __half* Ch = (__half*)Cv;
                __half2 h0 = __float22half2_rn(make_float2(v00, v01));
                __half2 h1 = __float22half2_rn(make_float2(v10, v11));
                if (r0 < M)     *(__half2*)(Ch + (size_t)r0 * ldc + c) = h0;
                if (r0 + 8 < M) *(__half2*)(Ch + (size_t)(r0 + 8) * ldc + c) = h1;
            } else {
                float* Cf = (float*)Cv;
                float2 p0 = make_float2(v00, v01);
                float2 p1 = make_float2(v10, v11);
                if (STREAM_OUT) {
                    if (r0 < M)     __stcs((float2*)(Cf + (size_t)r0 * ldc + c), p0);
                    if (r0 + 8 < M) __stcs((float2*)(Cf + (size_t)(r0 + 8) * ldc + c), p1);
                } else {
                    if (r0 < M)     *(float2*)(Cf + (size_t)r0 * ldc + c) = p0;
                    if (r0 + 8 < M) *(float2*)(Cf + (size_t)(r0 + 8) * ldc + c) = p1;
                }
            }
        }
    }
}

// ---------------- streams/events/attrs created once ----------------
struct HxRes {
    cudaStream_t s0, s1;
    cudaEvent_t ev_fork, ev_j0, ev_j1;
    HxRes() {
        cudaStreamCreateWithFlags(&s0, cudaStreamNonBlocking);
        cudaStreamCreateWithFlags(&s1, cudaStreamNonBlocking);
        cudaEventCreateWithFlags(&ev_fork, cudaEventDisableTiming);
        cudaEventCreateWithFlags(&ev_j0,   cudaEventDisableTiming);
        cudaEventCreateWithFlags(&ev_j1,   cudaEventDisableTiming);
        cudaFuncSetAttribute((const void*)k_gemm_f16<0,1,0>, cudaFuncAttributeMaxDynamicSharedMemorySize, 65536);
        cudaFuncSetAttribute((const void*)k_gemm_f16<1,1,0>, cudaFuncAttributeMaxDynamicSharedMemorySize, 65536);
        cudaFuncSetAttribute((const void*)k_gemm_f16<0,0,1>, cudaFuncAttributeMaxDynamicSharedMemorySize, 65536);
    }
};
static HxRes g_hx;

// ---------------- per-branch prep kernels ----------------
__global__ void k_halfcpy(const float* __restrict__ in, __half* __restrict__ out, int n4) {
    int i = blockIdx.x * blockDim.x + threadIdx.x;
    if (i < n4) {
        float4 v = ((const float4*)in)[i];
        __half2 h0 = __float22half2_rn(make_float2(v.x, v.y));
        __half2 h1 = __float22half2_rn(make_float2(v.z, v.w));
        ((uint2*)out)[i] = make_uint2(*(uint32_t*)&h0, *(uint32_t*)&h1);
    }
}

// W [L][K][N] f32 -> W^T [L][N][K] half
__global__ void k_halfT(const float* __restrict__ in, __half* __restrict__ out, int total) {
    int idx = blockIdx.x * blockDim.x + threadIdx.x;
    if (idx < total) {
        int l = idx >> 16;
        int rem = idx & 65535;
        int k = rem >> 8, n = rem & 255;
        out[(size_t)l * 65536 + n * 256 + k] = __float2half(in[idx]);
    }
}

__global__ void k_init1(int b) {
    int i = blockIdx.x * blockDim.x + threadIdx.x;
    if (i < NN_NODE) { g_dinv[b][i] = 1.0f; g_cnt[b][i] = 0; }
}

__global__ void k_deg1(const int* __restrict__ edges, const float* __restrict__ w, int b) {
    int e = blockIdx.x * blockDim.x + threadIdx.x;
    if (e < E_NUM) {
        int dst = edges[E_NUM + e];
        atomicAdd(&g_dinv[b][dst], w[e]);
        atomicAdd(&g_cnt[b][dst], 1);
    }
}

// scan (+ fused rsqrt)
__global__ void k_scan1(int b) {
    __shared__ int wsum[32];
    __shared__ int chunk_base;
    int tid = threadIdx.x, lane = tid & 31, w = tid >> 5;
    if (tid == 0) chunk_base = 0;
    __syncthreads();
    for (int c0 = 0; c0 < NN_NODE; c0 += 1024) {
        int idx = c0 + tid;
        int v = (idx < NN_NODE) ? g_cnt[b][idx] : 0;
        if (idx < NN_NODE) g_dinv[b][idx] = rsqrtf(g_dinv[b][idx]);
        int sc = v;
        #pragma unroll
        for (int off = 1; off < 32; off <<= 1) {
            int u = __shfl_up_sync(0xffffffffu, sc, off);
            if (lane >= off) sc += u;
        }
        if (lane == 31) wsum[w] = sc;
        __syncthreads();
        if (w == 0) {
            int tv = wsum[lane];
            #pragma unroll
            for (int off = 1; off < 32; off <<= 1) {
                int u = __shfl_up_sync(0xffffffffu, tv, off);
                if (lane >= off) tv += u;
            }
            wsum[lane] = tv;
        }
        __syncthreads();
        int total = wsum[31];
        int excl = chunk_base + (w ? wsum[w - 1] : 0) + sc - v;
        if (idx < NN_NODE) { g_rowptr[b][idx] = excl; g_cnt[b][idx] = 0; }
        __syncthreads();
        if (tid == 0) chunk_base += total;
        __syncthreads();
    }
    if (tid == 0) g_rowptr[b][NN_NODE] = chunk_base;
}

__global__ void k_fill1(const int* __restrict__ edges, const float* __restrict__ w, int b) {
    int e = blockIdx.x * blockDim.x + threadIdx.x;
    if (e < E_NUM) {
        int s = edges[e];
        int d = edges[E_NUM + e];
        int pos = g_rowptr[b][d] + atomicAdd(&g_cnt[b][d], 1);
        g_csr_src[b][pos] = s;
        g_csr_norm[b][pos] = g_dinv[b][s] * w[e] * g_dinv[b][d];
    }
}

// ---------------- aggregation: warp-per-node, uint4 gathers, unroll-4, no atomics ----------------
__global__ __launch_bounds__(64) void k_aggregate(const __half* __restrict__ h1, int b,
                                                  const float* __restrict__ bias, int layer) {
    const int w = threadIdx.x >> 5;
    const int l = threadIdx.x & 31;          // lane: 8 halves = 1 uint4
    const int v = blockIdx.x * 2 + w;        // 5000 * 2 = 10000 exact
    const uint4* h1v = (const uint4*)h1;     // 32 uint4 per row

    float dv = g_dinv[b][v];
    float sw = dv * dv;
    uint4 raw = h1v[(size_t)v * 32 + l];
    float acc[8];
    {
        float2 c0 = __half22float2(*(__half2*)&raw.x);
        float2 c1 = __half22float2(*(__half2*)&raw.y);
        float2 c2 = __half22float2(*(__half2*)&raw.z);
        float2 c3 = __half22float2(*(__half2*)&raw.w);
        acc[0] = sw * c0.x; acc[1] = sw * c0.y; acc[2] = sw * c1.x; acc[3] = sw * c1.y;
        acc[4] = sw * c2.x; acc[5] = sw * c2.y; acc[6] = sw * c3.x; acc[7] = sw * c3.y;
    }

    int e = g_rowptr[b][v];
    int e2 = g_rowptr[b][v + 1];
    const int*   srcs  = g_csr_src[b];
    const float* norms = g_csr_norm[b];

    auto fma8 = [&](float n, uint4 r) {
        float2 c0 = __half22float2(*(__half2*)&r.x);
        float2 c1 = __half22float2(*(__half2*)&r.y);
        float2 c2 = __half22float2(*(__half2*)&r.z);
        float2 c3 = __half22float2(*(__half2*)&r.w);
        acc[0] += n * c0.x; acc[1] += n * c0.y; acc[2] += n * c1.x; acc[3] += n * c1.y;
        acc[4] += n * c2.x; acc[5] += n * c2.y; acc[6] += n * c3.x; acc[7] += n * c3.y;
    };

    for (; e + 4 <= e2; e += 4) {
        int u0 = srcs[e], u1 = srcs[e + 1], u2 = srcs[e + 2], u3 = srcs[e + 3];
        float n0 = norms[e], n1 = norms[e + 1], n2 = norms[e + 2], n3 = norms[e + 3];
        uint4 r0 = h1v[(size_t)u0 * 32 + l];
        uint4 r1 = h1v[(size_t)u1 * 32 + l];
        uint4 r2 = h1v[(size_t)u2 * 32 + l];
        uint4 r3 = h1v[(size_t)u3 * 32 + l];
        fma8(n0, r0); fma8(n1, r1); fma8(n2, r2); fma8(n3, r3);
    }
    for (; e < e2; e++) fma8(norms[e], h1v[(size_t)srcs[e] * 32 + l]);

    const float4* bf = (const float4*)bias;
    float4 b0 = bf[l * 2], b1 = bf[l * 2 + 1];
    acc[0] = fmaxf(acc[0] + b0.x, 0.f); acc[1] = fmaxf(acc[1] + b0.y, 0.f);
    acc[2] = fmaxf(acc[2] + b0.z, 0.f); acc[3] = fmaxf(acc[3] + b0.w, 0.f);
    acc[4] = fmaxf(acc[4] + b1.x, 0.f); acc[5] = fmaxf(acc[5] + b1.y, 0.f);
    acc[6] = fmaxf(acc[6] + b1.z, 0.f); acc[7] = fmaxf(acc[7] + b1.w, 0.f);

    __half2 h0 = __float22half2_rn(make_float2(acc[0], acc[1]));
    __half2 h1p = __float22half2_rn(make_float2(acc[2], acc[3]));
    __half2 h2 = __float22half2_rn(make_float2(acc[4], acc[5]));
    __half2 h3 = __float22half2_rn(make_float2(acc[6], acc[7]));
    uint4 outv = make_uint4(*(uint32_t*)&h0, *(uint32_t*)&h1p, *(uint32_t*)&h2, *(uint32_t*)&h3);
    *(uint4*)&g_feats[b][(size_t)v * KTOT + layer * FDIM + l * 8] = outv;

    float m = acc[0];
    #pragma unroll
    for (int q = 1; q < 8; q++) m = fmaxf(m, acc[q]);
    #pragma unroll
    for (int off = 16; off > 0; off >>= 1)
        m = fmaxf(m, __shfl_xor_sync(0xffffffffu, m, off));
    if (l == 0) g_nodemax[b][layer][v] = m;
}

// ---------------- attention FC (with node-max reduction) + effective conv weights ----------------
__global__ void k_attfc2(const float* __restrict__ fc1w, const float* __restrict__ fc1b,
                         const float* __restrict__ fc2w, const float* __restrict__ fc2b, int b) {
    __shared__ float red[256];
    __shared__ float amax_s[NLAYERS];
    int tid = threadIdx.x;
    for (int c = 0; c < NLAYERS; c++) {
        float m = 0.f;
        for (int i = tid; i < NN_NODE; i += 256) m = fmaxf(m, g_nodemax[b][c][i]);
        red[tid] = m;
        __syncthreads();
        for (int o = 128; o > 0; o >>= 1) {
            if (tid < o) red[tid] = fmaxf(red[tid], red[tid + o]);
            __syncthreads();
        }
        if (tid == 0) amax_s[c] = red[0];
        __syncthreads();
    }
    if (tid == 0) {
        float t[5 * NLAYERS];
        for (int j = 0; j < 5 * NLAYERS; j++) {
            float s = fc1b[j];
            for (int c = 0; c < NLAYERS; c++) s += fc1w[j * NLAYERS + c] * amax_s[c];
            t[j] = fmaxf(s, 0.f);
        }
        for (int c = 0; c < NLAYERS; c++) {
            float s = fc2b[c];
            for (int j = 0; j < 5 * NLAYERS; j++) s += fc2w[c * (5 * NLAYERS) + j] * t[j];
            g_atts[b][c] = 1.0f / (1.0f + expf(-s));
        }
    }
}

__global__ void k_weff(const float* __restrict__ cw, int b) {
    int idx = blockIdx.x * blockDim.x + threadIdx.x;
    if (idx < OC * KTOT) {
        int c = (idx % KTOT) >> 8;
        g_weff[b][idx] = __float2half(cw[idx] * g_atts[b][c]);
    }
}

// ---------------- launch ----------------
extern "C" void kernel_launch(void* const* d_in, const int* in_sizes, int n_in,
                              void* d_out, int out_size) {
    const float* x_m    = (const float*)d_in[0];
    const float* x_d    = (const float*)d_in[1];
    const float* w_m    = (const float*)d_in[2];
    const float* w_d    = (const float*)d_in[3];
    const float* Wx     = (const float*)d_in[4];
    const float* bx     = (const float*)d_in[5];
    const float* Wy     = (const float*)d_in[6];
    const float* by     = (const float*)d_in[7];
    const float* fc1x_w = (const float*)d_in[8];
    const float* fc1x_b = (const float*)d_in[9];
    const float* fc2x_w = (const float*)d_in[10];
    const float* fc2x_b = (const float*)d_in[11];
    const float* fc1y_w = (const float*)d_in[12];
    const float* fc1y_b = (const float*)d_in[13];
    const float* fc2y_w = (const float*)d_in[14];
    const float* fc2y_b = (const float*)d_in[15];
    const float* cnnx_w = (const float*)d_in[16];
    const float* cnnx_b = (const float*)d_in[17];
    const float* cnny_w = (const float*)d_in[18];
    const float* cnny_b = (const float*)d_in[19];
    const int*   edges_m = (const int*)d_in[20];
    const int*   edges_d = (const int*)d_in[21];
    float* out = (float*)d_out;

    __half *p_h1, *p_feats, *p_weff, *p_emb, *p_xh, *p_wt;
    cudaGetSymbolAddress((void**)&p_h1,    g_h1);
    cudaGetSymbolAddress((void**)&p_feats, g_feats);
    cudaGetSymbolAddress((void**)&p_weff,  g_weff);
    cudaGetSymbolAddress((void**)&p_emb,   g_emb);
    cudaGetSymbolAddress((void**)&p_xh,    g_xh);
    cudaGetSymbolAddress((void**)&p_wt,    g_wt);

    __half* emb0 = p_emb;
    __half* emb1 = p_emb + (size_t)NN_NODE * OC;

    const int MT = (NN_NODE + 127) / 128;   // 79
    const int SM_F16 = 3 * (128 * 20 + 128 * 20) * 4;  // 61440

    cudaEventRecord(g_hx.ev_fork, 0);
    cudaStreamWaitEvent(g_hx.s0, g_hx.ev_fork, 0);
    cudaStreamWaitEvent(g_hx.s1, g_hx.ev_fork, 0);

    for (int b = 0; b < 2; b++) {
        cudaStream_t st = b ? g_hx.s1 : g_hx.s0;
        const int*   edges = b ? edges_d : edges_m;
        const float* w     = b ? w_d : w_m;
        const float* W     = b ? Wy : Wx;
        const float* bias  = b ? by : bx;
        const float* x0    = b ? x_d : x_m;
        const float* fc1w  = b ? fc1y_w : fc1x_w;
        const float* fc1b  = b ? fc1y_b : fc1x_b;
        const float* fc2w  = b ? fc2y_w : fc2x_w;
        const float* fc2b  = b ? fc2y_b : fc2x_b;
        const float* cw    = b ? cnny_w : cnnx_w;
        const float* cb    = b ? cnny_b : cnnx_b;
        __half* featsB = p_feats + (size_t)b * NN_NODE * KTOT;
        __half* h1B    = p_h1    + (size_t)b * NN_NODE * FDIM;
        __half* xhB    = p_xh    + (size_t)b * NN_NODE * FDIM;
        __half* wtB    = p_wt    + (size_t)b * NLAYERS * FDIM * FDIM;
        __half* weffB  = p_weff  + (size_t)b * OC * KTOT;
        __half* embB   = b ? emb1 : emb0;

        // fully per-branch prep on this branch's stream (no cross-stream deps)
        k_halfcpy<<<(NN_NODE * FDIM / 4 + 255) / 256, 256, 0, st>>>(x0, xhB, NN_NODE * FDIM / 4);
        k_halfT<<<(NLAYERS * FDIM * FDIM + 255) / 256, 256, 0, st>>>(W, wtB, NLAYERS * FDIM * FDIM);
        k_init1<<<(NN_NODE + 255) / 256, 256, 0, st>>>(b);
        k_deg1<<<E_NUM / 256, 256, 0, st>>>(edges, w, b);
        k_scan1<<<1, 1024, 0, st>>>(b);
        k_fill1<<<E_NUM / 256, 256, 0, st>>>(edges, w, b);

        const __half* hin = xhB;
        int lda = FDIM;
        for (int i = 0; i < NLAYERS; i++) {
            k_gemm_f16<0, 1, 0><<<dim3(FDIM / 128, MT), 256, SM_F16, st>>>(
                NN_NODE, FDIM, FDIM,
                hin, hin, lda,
                wtB + (size_t)i * FDIM * FDIM, wtB + (size_t)i * FDIM * FDIM, FDIM,
                h1B, h1B, FDIM, nullptr, nullptr);
            k_aggregate<<<NN_NODE / 2, 64, 0, st>>>(h1B, b, bias + (size_t)i * FDIM, i);
            hin = featsB + (size_t)i * FDIM;
            lda = KTOT;
        }

        // per-branch tail
        k_attfc2<<<1, 256, 0, st>>>(fc1w, fc1b, fc2w, fc2b, b);
        k_weff<<<(OC * KTOT + 255) / 256, 256, 0, st>>>(cw, b);
        k_gemm_f16<1, 1, 0><<<dim3(1, MT, 1), 256, SM_F16, st>>>(
            NN_NODE, OC, KTOT,
            featsB, featsB, KTOT,
            weffB, weffB, KTOT,
            embB, embB, OC,
            cb, cb);
    }

    cudaEventRecord(g_hx.ev_j0, g_hx.s0);
    cudaEventRecord(g_hx.ev_j1, g_hx.s1);
    cudaStreamWaitEvent(0, g_hx.ev_j0, 0);
    cudaStreamWaitEvent(0, g_hx.ev_j1, 0);

    k_gemm_f16<0, 0, 1><<<dim3(MT, MT, 1), 256, SM_F16>>>(
        NN_NODE, NN_NODE, OC,
        emb0, emb0, OC,
        emb1, emb1, OC,
        out, out, NN_NODE,
        nullptr, nullptr);
}

// round 16
// speedup vs baseline: 1.2071x; 1.0357x over previous
#include <cuda_runtime.h>
#include <cuda_fp16.h>
#include <math.h>
#include <stdint.h>

#define NN_NODE 10000
#define E_NUM   320000
#define FDIM    256
#define NLAYERS 5
#define OC      128
#define KTOT    (NLAYERS*FDIM)   // 1280

// ---------------- scratch ----------------
__device__ float g_dinv[2][NN_NODE];
__device__ int   g_cnt[2][NN_NODE];
__device__ int   g_rowptr[2][NN_NODE + 1];
__device__ int   g_csr_src[2][E_NUM];
__device__ float g_csr_norm[2][E_NUM];
__device__ __align__(16) __half g_feats[2][(size_t)NN_NODE * KTOT];
__device__ __align__(16) __half g_h1[2][(size_t)NN_NODE * FDIM];
__device__ __align__(16) __half g_xh[2][(size_t)NN_NODE * FDIM];
__device__ __align__(16) __half g_wt[2][(size_t)NLAYERS * FDIM * FDIM];
__device__ float g_nodemax[2][NLAYERS][NN_NODE];
__device__ float g_atts[2][NLAYERS];
__device__ __align__(16) __half g_weff[2][OC * KTOT];
__device__ __align__(16) __half g_emb[2][(size_t)NN_NODE * OC];

// ---------------- FP16 cp.async GEMM 128x128x32, 3-stage, optional z-batch ----------------
#define MMA_F16(d, a, b) \
  asm volatile("mma.sync.aligned.m16n8k16.row.col.f32.f16.f16.f32 " \
      "{%0,%1,%2,%3}, {%4,%5,%6,%7}, {%8,%9}, {%0,%1,%2,%3};" \
      : "+f"(d[0]), "+f"(d[1]), "+f"(d[2]), "+f"(d[3]) \
      : "r"(a[0]), "r"(a[1]), "r"(a[2]), "r"(a[3]), "r"(b[0]), "r"(b[1]))

__device__ __forceinline__ void cp16(uint32_t d, const void* s, bool p) {
    int sz = p ? 16 : 0;
    asm volatile("cp.async.cg.shared.global [%0], [%1], 16, %2;\n" :: "r"(d), "l"(s), "r"(sz));
}
__device__ __forceinline__ void cp_commit() { asm volatile("cp.async.commit_group;\n"); }
template <int N> __device__ __forceinline__ void cp_wait() {
    asm volatile("cp.async.wait_group %0;\n" :: "n"(N));
}

template <int BIAS, int OUT_HALF, int STREAM_OUT>
__global__ __launch_bounds__(256) void k_gemm_f16(
        int M, int N, int K,
        const __half* __restrict__ A0, const __half* __restrict__ A1, int lda,
        const __half* __restrict__ B0, const __half* __restrict__ B1, int ldb,
        void* __restrict__ C0, void* __restrict__ C1, int ldc,
        const float* __restrict__ bias0, const float* __restrict__ bias1) {
    constexpr int STAGES = 3;
    constexpr int LD32 = 20;
    constexpr int A_ST = 128 * LD32;
    constexpr int B_ST = 128 * LD32;
    extern __shared__ uint32_t smem[];
    uint32_t* As = smem;
    uint32_t* Bs = smem + STAGES * A_ST;

    const int bz = blockIdx.z;
    const __half* A = bz ? A1 : A0;
    const __half* B = bz ? B1 : B0;
    void* Cv = bz ? C1 : C0;
    const float* bias = bz ? bias1 : bias0;

    const int tid = threadIdx.x;
    const int wid = tid >> 5;
    const int lane = tid & 31;
    const int g = lane >> 2, t = lane & 3;
    const int wm = wid >> 1, wn = wid & 1;
    const int i0 = blockIdx.y * 128, j0 = blockIdx.x * 128;

    const int ar = tid >> 1, akc = (tid & 1) * 16;

    const bool a_ok = (i0 + ar < M);
    const __half* a_src = A + (size_t)(a_ok ? i0 + ar : M - 1) * lda + akc;
    const bool b_ok = (j0 + ar < N);
    const __half* b_src = B + (size_t)(b_ok ? j0 + ar : N - 1) * ldb + akc;

    uint32_t sa_base = (uint32_t)__cvta_generic_to_shared(&As[ar * LD32 + akc / 2]);
    uint32_t sb_base = (uint32_t)__cvta_generic_to_shared(&Bs[ar * LD32 + akc / 2]);

    auto issue = [&](int s, int k0) {
        uint32_t da = sa_base + s * (A_ST * 4);
        const __half* pa = a_src + k0;
        cp16(da,      pa,     a_ok);
        cp16(da + 16, pa + 8, a_ok);
        uint32_t db = sb_base + s * (B_ST * 4);
        const __half* pb = b_src + k0;
        cp16(db,      pb,     b_ok);
        cp16(db + 16, pb + 8, b_ok);
        cp_commit();
    };

    float acc[2][8][4];
    #pragma unroll
    for (int mt = 0; mt < 2; mt++)
        #pragma unroll
        for (int nt = 0; nt < 8; nt++)
            #pragma unroll
            for (int q = 0; q < 4; q++) acc[mt][nt][q] = 0.0f;

    auto compute = [&](int s) {
        const uint32_t* Ab = As + s * A_ST;
        const uint32_t* Bb = Bs + s * B_ST;
        #pragma unroll
        for (int c = 0; c < 2; c++) {
            const int base = c * 8;
            uint32_t af[2][4];
            #pragma unroll
            for (int mt = 0; mt < 2; mt++) {
                int r = wm * 32 + mt * 16;
                af[mt][0] = Ab[(r + g) * LD32 + base + t];
                af[mt][1] = Ab[(r + g + 8) * LD32 + base + t];
                af[mt][2] = Ab[(r + g) * LD32 + base + t + 4];
                af[mt][3] = Ab[(r + g + 8) * LD32 + base + t + 4];
            }
            uint32_t bf[8][2];
            #pragma unroll
            for (int nt = 0; nt < 8; nt++) {
                int n = wn * 64 + nt * 8 + g;
                bf[nt][0] = Bb[n * LD32 + base + t];
                bf[nt][1] = Bb[n * LD32 + base + t + 4];
            }
            #pragma unroll
            for (int mt = 0; mt < 2; mt++)
                #pragma unroll
                for (int nt = 0; nt < 8; nt++)
                    MMA_F16(acc[mt][nt], af[mt], bf[nt]);
        }
    };

    const int ktiles = K / 32;
    issue(0, 0);
    if (ktiles > 1) issue(1, 32);
    for (int i = 0; i < ktiles; i++) {
        if (i < ktiles - 1) cp_wait<STAGES - 2>(); else cp_wait<0>();
        __syncthreads();
        int pf = i + STAGES - 1;
        if (pf < ktiles) issue(pf % STAGES, pf * 32);
        compute(i % STAGES);
    }

    #pragma unroll
    for (int mt = 0; mt < 2; mt++) {
        int r0 = i0 + wm * 32 + mt * 16 + g;
        #pragma unroll
        for (int nt = 0; nt < 8; nt++) {
            int c = j0 + wn * 64 + nt * 8 + 2 * t;
            if (c >= N) continue;
            float bx0 = 0.f, bx1 = 0.f;
            if (BIAS) { bx0 = bias[c]; bx1 = bias[c + 1]; }
            float v00 = acc[mt][nt][0] + bx0, v01 = acc[mt][nt][1] + bx1;
            float v10 = acc[mt][nt][2] + bx0, v11 = acc[mt][nt][3] + bx1;
            if (OUT_HALF) {
                __half* Ch = (__half*)Cv;
                __half2 h0 = __float22half2_rn(make_float2(v00, v01));
                __half2 h1 = __float22half2_rn(make_float2(v10, v11));
                if (r0 < M)     *(__half2*)(Ch + (size_t)r0 * ldc + c) = h0;
                if (r0 + 8 < M) *(__half2*)(Ch + (size_t)(r0 + 8) * ldc + c) = h1;
            } else {
                float* Cf = (float*)Cv;
                float2 p0 = make_float2(v00, v01);
                float2 p1 = make_float2(v10, v11);
                if (STREAM_OUT) {
                    if (r0 < M)     __stcs((float2*)(Cf + (size_t)r0 * ldc + c), p0);
                    if (r0 + 8 < M) __stcs((float2*)(Cf + (size_t)(r0 + 8) * ldc + c), p1);
                } else {
                    if (r0 < M)     *(float2*)(Cf + (size_t)r0 * ldc + c) = p0;
                    if (r0 + 8 < M) *(float2*)(Cf + (size_t)(r0 + 8) * ldc + c) = p1;
                }
            }
        }
    }
}

// ---------------- streams/events/attrs created once ----------------
struct HxRes {
    cudaStream_t s0, s1;
    cudaEvent_t ev_fork, ev_h, ev_csr, ev_j0, ev_j1;
    HxRes() {
        cudaStreamCreateWithFlags(&s0, cudaStreamNonBlocking);
        cudaStreamCreateWithFlags(&s1, cudaStreamNonBlocking);
        cudaEventCreateWithFlags(&ev_fork, cudaEventDisableTiming);
        cudaEventCreateWithFlags(&ev_h,    cudaEventDisableTiming);
        cudaEventCreateWithFlags(&ev_csr,  cudaEventDisableTiming);
        cudaEventCreateWithFlags(&ev_j0,   cudaEventDisableTiming);
        cudaEventCreateWithFlags(&ev_j1,   cudaEventDisableTiming);
        cudaFuncSetAttribute((const void*)k_gemm_f16<0,1,0>, cudaFuncAttributeMaxDynamicSharedMemorySize, 65536);
        cudaFuncSetAttribute((const void*)k_gemm_f16<1,1,0>, cudaFuncAttributeMaxDynamicSharedMemorySize, 65536);
        cudaFuncSetAttribute((const void*)k_gemm_f16<0,0,1>, cudaFuncAttributeMaxDynamicSharedMemorySize, 65536);
    }
};
static HxRes g_hx;

// ---------------- prep kernels ----------------
__global__ void k_init() {
    int i = blockIdx.x * blockDim.x + threadIdx.x;
    if (i < NN_NODE) {
        g_dinv[0][i] = 1.0f; g_dinv[1][i] = 1.0f;
        g_cnt[0][i] = 0;     g_cnt[1][i] = 0;
    }
}

__global__ void k_halfcpy_b(const float* __restrict__ in0, const float* __restrict__ in1,
                            int n4) {
    int b = blockIdx.y;
    const float* in = b ? in1 : in0;
    __half* out = g_xh[b];
    int i = blockIdx.x * blockDim.x + threadIdx.x;
    if (i < n4) {
        float4 v = ((const float4*)in)[i];
        __half2 h0 = __float22half2_rn(make_float2(v.x, v.y));
        __half2 h1 = __float22half2_rn(make_float2(v.z, v.w));
        ((uint2*)out)[i] = make_uint2(*(uint32_t*)&h0, *(uint32_t*)&h1);
    }
}

// W [L][K][N] f32 -> W^T [L][N][K] half
__global__ void k_halfT_b(const float* __restrict__ in0, const float* __restrict__ in1,
                          int total) {
    int b = blockIdx.y;
    const float* in = b ? in1 : in0;
    __half* out = g_wt[b];
    int idx = blockIdx.x * blockDim.x + threadIdx.x;
    if (idx < total) {
        int l = idx >> 16;
        int rem = idx & 65535;
        int k = rem >> 8, n = rem & 255;
        out[(size_t)l * 65536 + n * 256 + k] = __float2half(in[idx]);
    }
}

__global__ void k_deg_cnt_b(const int* __restrict__ e0, const int* __restrict__ e1,
                            const float* __restrict__ w0, const float* __restrict__ w1) {
    int b = blockIdx.y;
    const int* edges = b ? e1 : e0;
    const float* w = b ? w1 : w0;
    int e = blockIdx.x * blockDim.x + threadIdx.x;
    if (e < E_NUM) {
        int dst = edges[E_NUM + e];
        atomicAdd(&g_dinv[b][dst], w[e]);
        atomicAdd(&g_cnt[b][dst], 1);
    }
}

__global__ void k_scan() {
    int b = blockIdx.x;
    __shared__ int wsum[32];
    __shared__ int chunk_base;
    int tid = threadIdx.x, lane = tid & 31, w = tid >> 5;
    if (tid == 0) chunk_base = 0;
    __syncthreads();
    for (int c0 = 0; c0 < NN_NODE; c0 += 1024) {
        int idx = c0 + tid;
        int v = (idx < NN_NODE) ? g_cnt[b][idx] : 0;
        if (idx < NN_NODE) g_dinv[b][idx] = rsqrtf(g_dinv[b][idx]);
        int sc = v;
        #pragma unroll
        for (int off = 1; off < 32; off <<= 1) {
            int u = __shfl_up_sync(0xffffffffu, sc, off);
            if (lane >= off) sc += u;
        }
        if (lane == 31) wsum[w] = sc;
        __syncthreads();
        if (w == 0) {
            int tv = wsum[lane];
            #pragma unroll
            for (int off = 1; off < 32; off <<= 1) {
                int u = __shfl_up_sync(0xffffffffu, tv, off);
                if (lane >= off) tv += u;
            }
            wsum[lane] = tv;
        }
        __syncthreads();
        int total = wsum[31];
        int excl = chunk_base + (w ? wsum[w - 1] : 0) + sc - v;
        if (idx < NN_NODE) { g_rowptr[b][idx] = excl; g_cnt[b][idx] = 0; }
        __syncthreads();
        if (tid == 0) chunk_base += total;
        __syncthreads();
    }
    if (tid == 0) g_rowptr[b][NN_NODE] = chunk_base;
}

__global__ void k_fill_b(const int* __restrict__ e0, const int* __restrict__ e1,
                         const float* __restrict__ w0, const float* __restrict__ w1) {
    int b = blockIdx.y;
    const int* edges = b ? e1 : e0;
    const float* w = b ? w1 : w0;
    int e = blockIdx.x * blockDim.x + threadIdx.x;
    if (e < E_NUM) {
        int s = edges[e];
        int d = edges[E_NUM + e];
        int pos = g_rowptr[b][d] + atomicAdd(&g_cnt[b][d], 1);
        g_csr_src[b][pos] = s;
        g_csr_norm[b][pos] = g_dinv[b][s] * w[e] * g_dinv[b][d];
    }
}

// ---------------- aggregation: warp-per-node, uint4 gathers, no atomics ----------------
__global__ __launch_bounds__(64) void k_aggregate(const __half* __restrict__ h1, int b,
                                                  const float* __restrict__ bias, int layer) {
    const int w = threadIdx.x >> 5;          // warp in block
    const int l = threadIdx.x & 31;          // lane: 8 halves = 1 uint4 per lane
    const int v = blockIdx.x * 2 + w;        // node (grid 5000 * 2 = 10000 exact)
    const uint4* h1v = (const uint4*)h1;     // 32 uint4 per row

    float dv = g_dinv[b][v];
    float sw = dv * dv;
    uint4 raw = h1v[(size_t)v * 32 + l];
    float acc[8];
    {
        float2 c0 = __half22float2(*(__half2*)&raw.x);
        float2 c1 = __half22float2(*(__half2*)&raw.y);
        float2 c2 = __half22float2(*(__half2*)&raw.z);
        float2 c3 = __half22float2(*(__half2*)&raw.w);
        acc[0] = sw * c0.x; acc[1] = sw * c0.y; acc[2] = sw * c1.x; acc[3] = sw * c1.y;
        acc[4] = sw * c2.x; acc[5] = sw * c2.y; acc[6] = sw * c3.x; acc[7] = sw * c3.y;
    }

    int e = g_rowptr[b][v];
    int e2 = g_rowptr[b][v + 1];
    const int*   srcs  = g_csr_src[b];
    const float* norms = g_csr_norm[b];

    auto fma8 = [&](float n, uint4 r) {
        float2 c0 = __half22float2(*(__half2*)&r.x);
        float2 c1 = __half22float2(*(__half2*)&r.y);
        float2 c2 = __half22float2(*(__half2*)&r.z);
        float2 c3 = __half22float2(*(__half2*)&r.w);
        acc[0] += n * c0.x; acc[1] += n * c0.y; acc[2] += n * c1.x; acc[3] += n * c1.y;
        acc[4] += n * c2.x; acc[5] += n * c2.y; acc[6] += n * c3.x; acc[7] += n * c3.y;
    };

    for (; e + 4 <= e2; e += 4) {
        int u0 = srcs[e], u1 = srcs[e + 1], u2 = srcs[e + 2], u3 = srcs[e + 3];
        float n0 = norms[e], n1 = norms[e + 1], n2 = norms[e + 2], n3 = norms[e + 3];
        uint4 r0 = h1v[(size_t)u0 * 32 + l];
        uint4 r1 = h1v[(size_t)u1 * 32 + l];
        uint4 r2 = h1v[(size_t)u2 * 32 + l];
        uint4 r3 = h1v[(size_t)u3 * 32 + l];
        fma8(n0, r0); fma8(n1, r1); fma8(n2, r2); fma8(n3, r3);
    }
    for (; e < e2; e++) fma8(norms[e], h1v[(size_t)srcs[e] * 32 + l]);

    const float4* bf = (const float4*)bias;
    float4 b0 = bf[l * 2], b1 = bf[l * 2 + 1];
    acc[0] = fmaxf(acc[0] + b0.x, 0.f); acc[1] = fmaxf(acc[1] + b0.y, 0.f);
    acc[2] = fmaxf(acc[2] + b0.z, 0.f); acc[3] = fmaxf(acc[3] + b0.w, 0.f);
    acc[4] = fmaxf(acc[4] + b1.x, 0.f); acc[5] = fmaxf(acc[5] + b1.y, 0.f);
    acc[6] = fmaxf(acc[6] + b1.z, 0.f); acc[7] = fmaxf(acc[7] + b1.w, 0.f);

    __half2 h0 = __float22half2_rn(make_float2(acc[0], acc[1]));
    __half2 h1p = __float22half2_rn(make_float2(acc[2], acc[3]));
    __half2 h2 = __float22half2_rn(make_float2(acc[4], acc[5]));
    __half2 h3 = __float22half2_rn(make_float2(acc[6], acc[7]));
    uint4 outv = make_uint4(*(uint32_t*)&h0, *(uint32_t*)&h1p, *(uint32_t*)&h2, *(uint32_t*)&h3);
    *(uint4*)&g_feats[b][(size_t)v * KTOT + layer * FDIM + l * 8] = outv;

    float m = acc[0];
    #pragma unroll
    for (int q = 1; q < 8; q++) m = fmaxf(m, acc[q]);
    #pragma unroll
    for (int off = 16; off > 0; off >>= 1)
        m = fmaxf(m, __shfl_xor_sync(0xffffffffu, m, off));
    if (l == 0) g_nodemax[b][layer][v] = m;
}

// ---------------- attention FC (with node-max reduction) + effective conv weights ----------------
__global__ void k_attfc2(const float* __restrict__ fc1w, const float* __restrict__ fc1b,
                         const float* __restrict__ fc2w, const float* __restrict__ fc2b, int b) {
    __shared__ float red[256];
    __shared__ float amax_s[NLAYERS];
    int tid = threadIdx.x;
    for (int c = 0; c < NLAYERS; c++) {
        float m = 0.f;
        for (int i = tid; i < NN_NODE; i += 256) m = fmaxf(m, g_nodemax[b][c][i]);
        red[tid] = m;
        __syncthreads();
        for (int o = 128; o > 0; o >>= 1) {
            if (tid < o) red[tid] = fmaxf(red[tid], red[tid + o]);
            __syncthreads();
        }
        if (tid == 0) amax_s[c] = red[0];
        __syncthreads();
    }
    if (tid == 0) {
        float t[5 * NLAYERS];
        for (int j = 0; j < 5 * NLAYERS; j++) {
            float s = fc1b[j];
            for (int c = 0; c < NLAYERS; c++) s += fc1w[j * NLAYERS + c] * amax_s[c];
            t[j] = fmaxf(s, 0.f);
        }
        for (int c = 0; c < NLAYERS; c++) {
            float s = fc2b[c];
            for (int j = 0; j < 5 * NLAYERS; j++) s += fc2w[c * (5 * NLAYERS) + j] * t[j];
            g_atts[b][c] = 1.0f / (1.0f + expf(-s));
        }
    }
}

__global__ void k_weff(const float* __restrict__ cw, int b) {
    int idx = blockIdx.x * blockDim.x + threadIdx.x;
    if (idx < OC * KTOT) {
        int c = (idx % KTOT) >> 8;
        g_weff[b][idx] = __float2half(cw[idx] * g_atts[b][c]);
    }
}

// ---------------- launch ----------------
extern "C" void kernel_launch(void* const* d_in, const int* in_sizes, int n_in,
                              void* d_out, int out_size) {
    const float* x_m    = (const float*)d_in[0];
    const float* x_d    = (const float*)d_in[1];
    const float* w_m    = (const float*)d_in[2];
    const float* w_d    = (const float*)d_in[3];
    const float* Wx     = (const float*)d_in[4];
    const float* bx     = (const float*)d_in[5];
    const float* Wy     = (const float*)d_in[6];
    const float* by     = (const float*)d_in[7];
    const float* fc1x_w = (const float*)d_in[8];
    const float* fc1x_b = (const float*)d_in[9];
    const float* fc2x_w = (const float*)d_in[10];
    const float* fc2x_b = (const float*)d_in[11];
    const float* fc1y_w = (const float*)d_in[12];
    const float* fc1y_b = (const float*)d_in[13];
    const float* fc2y_w = (const float*)d_in[14];
    const float* fc2y_b = (const float*)d_in[15];
    const float* cnnx_w = (const float*)d_in[16];
    const float* cnnx_b = (const float*)d_in[17];
    const float* cnny_w = (const float*)d_in[18];
    const float* cnny_b = (const float*)d_in[19];
    const int*   edges_m = (const int*)d_in[20];
    const int*   edges_d = (const int*)d_in[21];
    float* out = (float*)d_out;

    __half *p_h1, *p_feats, *p_weff, *p_emb, *p_xh, *p_wt;
    cudaGetSymbolAddress((void**)&p_h1,    g_h1);
    cudaGetSymbolAddress((void**)&p_feats, g_feats);
    cudaGetSymbolAddress((void**)&p_weff,  g_weff);
    cudaGetSymbolAddress((void**)&p_emb,   g_emb);
    cudaGetSymbolAddress((void**)&p_xh,    g_xh);
    cudaGetSymbolAddress((void**)&p_wt,    g_wt);

    __half* emb0 = p_emb;
    __half* emb1 = p_emb + (size_t)NN_NODE * OC;

    const int MT = (NN_NODE + 127) / 128;   // 79
    const int SM_F16 = 3 * (128 * 20 + 128 * 20) * 4;  // 61440

    cudaEventRecord(g_hx.ev_fork, 0);
    cudaStreamWaitEvent(g_hx.s0, g_hx.ev_fork, 0);
    cudaStreamWaitEvent(g_hx.s1, g_hx.ev_fork, 0);

    // s0: conversions (needed by GEMM0 of both branches)
    k_halfcpy_b<<<dim3((NN_NODE * FDIM / 4 + 255) / 256, 2), 256, 0, g_hx.s0>>>(x_m, x_d, NN_NODE * FDIM / 4);
    k_halfT_b<<<dim3((NLAYERS * FDIM * FDIM + 255) / 256, 2), 256, 0, g_hx.s0>>>(Wx, Wy, NLAYERS * FDIM * FDIM);
    cudaEventRecord(g_hx.ev_h, g_hx.s0);

    // s1: CSR build (needed only by aggregates)
    k_init<<<(NN_NODE + 255) / 256, 256, 0, g_hx.s1>>>();
    k_deg_cnt_b<<<dim3(E_NUM / 256, 2), 256, 0, g_hx.s1>>>(edges_m, edges_d, w_m, w_d);
    k_scan<<<2, 1024, 0, g_hx.s1>>>();
    k_fill_b<<<dim3(E_NUM / 256, 2), 256, 0, g_hx.s1>>>(edges_m, edges_d, w_m, w_d);
    cudaEventRecord(g_hx.ev_csr, g_hx.s1);

    // cross deps: s1's GEMM0 needs conversions; s0's first aggregate needs CSR
    cudaStreamWaitEvent(g_hx.s1, g_hx.ev_h, 0);

    for (int b = 0; b < 2; b++) {
        cudaStream_t st = b ? g_hx.s1 : g_hx.s0;
        const float* bias  = b ? by : bx;
        const float* fc1w  = b ? fc1y_w : fc1x_w;
        const float* fc1b  = b ? fc1y_b : fc1x_b;
        const float* fc2w  = b ? fc2y_w : fc2x_w;
        const float* fc2b  = b ? fc2y_b : fc2x_b;
        const float* cw    = b ? cnny_w : cnnx_w;
        const float* cb    = b ? cnny_b : cnnx_b;
        __half* featsB = p_feats + (size_t)b * NN_NODE * KTOT;
        __half* h1B    = p_h1    + (size_t)b * NN_NODE * FDIM;
        __half* xhB    = p_xh    + (size_t)b * NN_NODE * FDIM;
        __half* wtB    = p_wt    + (size_t)b * NLAYERS * FDIM * FDIM;
        __half* weffB  = p_weff  + (size_t)b * OC * KTOT;
        __half* embB   = b ? emb1 : emb0;

        const __half* hin = xhB;
        int lda = FDIM;
        for (int i = 0; i < NLAYERS; i++) {
            k_gemm_f16<0, 1, 0><<<dim3(FDIM / 128, MT), 256, SM_F16, st>>>(
                NN_NODE, FDIM, FDIM,
                hin, hin, lda,
                wtB + (size_t)i * FDIM * FDIM, wtB + (size_t)i * FDIM * FDIM, FDIM,
                h1B, h1B, FDIM, nullptr, nullptr);
            if (b == 0 && i == 0) cudaStreamWaitEvent(g_hx.s0, g_hx.ev_csr, 0);
            k_aggregate<<<NN_NODE / 2, 64, 0, st>>>(h1B, b, bias + (size_t)i * FDIM, i);
            hin = featsB + (size_t)i * FDIM;
            lda = KTOT;
        }

        // per-branch tail starts as soon as this branch's layers finish
        k_attfc2<<<1, 256, 0, st>>>(fc1w, fc1b, fc2w, fc2b, b);
        k_weff<<<(OC * KTOT + 255) / 256, 256, 0, st>>>(cw, b);
        k_gemm_f16<1, 1, 0><<<dim3(1, MT, 1), 256, SM_F16, st>>>(
            NN_NODE, OC, KTOT,
            featsB, featsB, KTOT,
            weffB, weffB, KTOT,
            embB, embB, OC,
            cb, cb);
    }

    cudaEventRecord(g_hx.ev_j0, g_hx.s0);
    cudaEventRecord(g_hx.ev_j1, g_hx.s1);
    cudaStreamWaitEvent(0, g_hx.ev_j0, 0);
    cudaStreamWaitEvent(0, g_hx.ev_j1, 0);

    k_gemm_f16<0, 0, 1><<<dim3(MT, MT, 1), 256, SM_F16>>>(
        NN_NODE, NN_NODE, OC,
        emb0, emb0, OC,
        emb1, emb1, OC,
        out, out, NN_NODE,
        nullptr, nullptr);
}

// round 17
// speedup vs baseline: 1.2120x; 1.0041x over previous
#include <cuda_runtime.h>
#include <cuda_fp16.h>
#include <math.h>
#include <stdint.h>

#define NN_NODE 10000
#define E_NUM   320000
#define FDIM    256
#define NLAYERS 5
#define OC      128
#define KTOT    (NLAYERS*FDIM)   // 1280

// ---------------- scratch ----------------
__device__ float g_dinv[2][NN_NODE];
__device__ int   g_cnt[2][NN_NODE];
__device__ int   g_rowptr[2][NN_NODE + 1];
__device__ int   g_csr_src[2][E_NUM];
__device__ float g_csr_norm[2][E_NUM];
__device__ __align__(16) __half g_feats[2][(size_t)NN_NODE * KTOT];
__device__ __align__(16) __half g_h1[2][(size_t)NN_NODE * FDIM];
__device__ __align__(16) __half g_xh[2][(size_t)NN_NODE * FDIM];
__device__ __align__(16) __half g_wt[2][(size_t)NLAYERS * FDIM * FDIM];
__device__ float g_nodemax[2][NLAYERS][NN_NODE];
__device__ float g_atts[2][NLAYERS];
__device__ __align__(16) __half g_weff[2][OC * KTOT];
__device__ __align__(16) __half g_emb[2][(size_t)NN_NODE * OC];

// ---------------- FP16 cp.async GEMM 128x128x32, 3-stage, optional z-batch ----------------
#define MMA_F16(d, a, b) \
  asm volatile("mma.sync.aligned.m16n8k16.row.col.f32.f16.f16.f32 " \
      "{%0,%1,%2,%3}, {%4,%5,%6,%7}, {%8,%9}, {%0,%1,%2,%3};" \
      : "+f"(d[0]), "+f"(d[1]), "+f"(d[2]), "+f"(d[3]) \
      : "r"(a[0]), "r"(a[1]), "r"(a[2]), "r"(a[3]), "r"(b[0]), "r"(b[1]))

__device__ __forceinline__ void cp16(uint32_t d, const void* s, bool p) {
    int sz = p ? 16 : 0;
    asm volatile("cp.async.cg.shared.global [%0], [%1], 16, %2;\n" :: "r"(d), "l"(s), "r"(sz));
}
__device__ __forceinline__ void cp_commit() { asm volatile("cp.async.commit_group;\n"); }
template <int N> __device__ __forceinline__ void cp_wait() {
    asm volatile("cp.async.wait_group %0;\n" :: "n"(N));
}

template <int BIAS, int OUT_HALF, int STREAM_OUT>
__global__ __launch_bounds__(256) void k_gemm_f16(
        int M, int N, int K,
        const __half* __restrict__ A0, const __half* __restrict__ A1, int lda,
        const __half* __restrict__ B0, const __half* __restrict__ B1, int ldb,
        void* __restrict__ C0, void* __restrict__ C1, int ldc,
        const float* __restrict__ bias0, const float* __restrict__ bias1) {
    constexpr int STAGES = 3;
    constexpr int LD32 = 20;
    constexpr int A_ST = 128 * LD32;
    constexpr int B_ST = 128 * LD32;
    extern __shared__ uint32_t smem[];
    uint32_t* As = smem;
    uint32_t* Bs = smem + STAGES * A_ST;

    const int bz = blockIdx.z;
    const __half* A = bz ? A1 : A0;
    const __half* B = bz ? B1 : B0;
    void* Cv = bz ? C1 : C0;
    const float* bias = bz ? bias1 : bias0;

    const int tid = threadIdx.x;
    const int wid = tid >> 5;
    const int lane = tid & 31;
    const int g = lane >> 2, t = lane & 3;
    const int wm = wid >> 1, wn = wid & 1;
    const int i0 = blockIdx.y * 128, j0 = blockIdx.x * 128;

    const int ar = tid >> 1, akc = (tid & 1) * 16;

    const bool a_ok = (i0 + ar < M);
    const __half* a_src = A + (size_t)(a_ok ? i0 + ar : M - 1) * lda + akc;
    const bool b_ok = (j0 + ar < N);
    const __half* b_src = B + (size_t)(b_ok ? j0 + ar : N - 1) * ldb + akc;

    uint32_t sa_base = (uint32_t)__cvta_generic_to_shared(&As[ar * LD32 + akc / 2]);
    uint32_t sb_base = (uint32_t)__cvta_generic_to_shared(&Bs[ar * LD32 + akc / 2]);

    auto issue = [&](int s, int k0) {
        uint32_t da = sa_base + s * (A_ST * 4);
        const __half* pa = a_src + k0;
        cp16(da,      pa,     a_ok);
        cp16(da + 16, pa + 8, a_ok);
        uint32_t db = sb_base + s * (B_ST * 4);
        const __half* pb = b_src + k0;
        cp16(db,      pb,     b_ok);
        cp16(db + 16, pb + 8, b_ok);
        cp_commit();
    };

    float acc[2][8][4];
    #pragma unroll
    for (int mt = 0; mt < 2; mt++)
        #pragma unroll
        for (int nt = 0; nt < 8; nt++)
            #pragma unroll
            for (int q = 0; q < 4; q++) acc[mt][nt][q] = 0.0f;

    auto compute = [&](int s) {
        const uint32_t* Ab = As + s * A_ST;
        const uint32_t* Bb = Bs + s * B_ST;
        #pragma unroll
        for (int c = 0; c < 2; c++) {
            const int base = c * 8;
            uint32_t af[2][4];
            #pragma unroll
            for (int mt = 0; mt < 2; mt++) {
                int r = wm * 32 + mt * 16;
                af[mt][0] = Ab[(r + g) * LD32 + base + t];
                af[mt][1] = Ab[(r + g + 8) * LD32 + base + t];
                af[mt][2] = Ab[(r + g) * LD32 + base + t + 4];
                af[mt][3] = Ab[(r + g + 8) * LD32 + base + t + 4];
            }
            uint32_t bf[8][2];
            #pragma unroll
            for (int nt = 0; nt < 8; nt++) {
                int n = wn * 64 + nt * 8 + g;
                bf[nt][0] = Bb[n * LD32 + base + t];
                bf[nt][1] = Bb[n * LD32 + base + t + 4];
            }
            #pragma unroll
            for (int mt = 0; mt < 2; mt++)
                #pragma unroll
                for (int nt = 0; nt < 8; nt++)
                    MMA_F16(acc[mt][nt], af[mt], bf[nt]);
        }
    };

    const int ktiles = K / 32;
    issue(0, 0);
    if (ktiles > 1) issue(1, 32);
    for (int i = 0; i < ktiles; i++) {
        if (i < ktiles - 1) cp_wait<STAGES - 2>(); else cp_wait<0>();
        __syncthreads();
        int pf = i + STAGES - 1;
        if (pf < ktiles) issue(pf % STAGES, pf * 32);
        compute(i % STAGES);
    }

    #pragma unroll
    for (int mt = 0; mt < 2; mt++) {
        int r0 = i0 + wm * 32 + mt * 16 + g;
        #pragma unroll
        for (int nt = 0; nt < 8; nt++) {
            int c = j0 + wn * 64 + nt * 8 + 2 * t;
            if (c >= N) continue;
            float bx0 = 0.f, bx1 = 0.f;
            if (BIAS) { bx0 = bias[c]; bx1 = bias[c + 1]; }
            float v00 = acc[mt][nt][0] + bx0, v01 = acc[mt][nt][1] + bx1;
            float v10 = acc[mt][nt][2] + bx0, v11 = acc[mt][nt][3] + bx1;
            if (OUT_HALF) {
                __half* Ch = (__half*)Cv;
                __half2 h0 = __float22half2_rn(make_float2(v00, v01));
                __half2 h1 = __float22half2_rn(make_float2(v10, v11));
                if (r0 < M)     *(__half2*)(Ch + (size_t)r0 * ldc + c) = h0;
                if (r0 + 8 < M) *(__half2*)(Ch + (size_t)(r0 + 8) * ldc + c) = h1;
            } else {
                float* Cf = (float*)Cv;
                float2 p0 = make_float2(v00, v01);
                float2 p1 = make_float2(v10, v11);
                if (STREAM_OUT) {
                    if (r0 < M)     __stcs((float2*)(Cf + (size_t)r0 * ldc + c), p0);
                    if (r0 + 8 < M) __stcs((float2*)(Cf + (size_t)(r0 + 8) * ldc + c), p1);
                } else {
                    if (r0 < M)     *(float2*)(Cf + (size_t)r0 * ldc + c) = p0;
                    if (r0 + 8 < M) *(float2*)(Cf + (size_t)(r0 + 8) * ldc + c) = p1;
                }
            }
        }
    }
}

// ---------------- streams/events/attrs created once ----------------
struct HxRes {
    cudaStream_t s0, s1;
    cudaEvent_t ev_fork, ev_h, ev_csr, ev_j0, ev_j1;
    cudaEvent_t ev_gl[NLAYERS];
    HxRes() {
        cudaStreamCreateWithFlags(&s0, cudaStreamNonBlocking);
        cudaStreamCreateWithFlags(&s1, cudaStreamNonBlocking);
        cudaEventCreateWithFlags(&ev_fork, cudaEventDisableTiming);
        cudaEventCreateWithFlags(&ev_h,    cudaEventDisableTiming);
        cudaEventCreateWithFlags(&ev_csr,  cudaEventDisableTiming);
        cudaEventCreateWithFlags(&ev_j0,   cudaEventDisableTiming);
        cudaEventCreateWithFlags(&ev_j1,   cudaEventDisableTiming);
        for (int i = 0; i < NLAYERS; i++)
            cudaEventCreateWithFlags(&ev_gl[i], cudaEventDisableTiming);
        cudaFuncSetAttribute((const void*)k_gemm_f16<0,1,0>, cudaFuncAttributeMaxDynamicSharedMemorySize, 65536);
        cudaFuncSetAttribute((const void*)k_gemm_f16<1,1,0>, cudaFuncAttributeMaxDynamicSharedMemorySize, 65536);
        cudaFuncSetAttribute((const void*)k_gemm_f16<0,0,1>, cudaFuncAttributeMaxDynamicSharedMemorySize, 65536);
    }
};
static HxRes g_hx;

// ---------------- prep kernels ----------------
__global__ void k_init() {
    int i = blockIdx.x * blockDim.x + threadIdx.x;
    if (i < NN_NODE) {
        g_dinv[0][i] = 1.0f; g_dinv[1][i] = 1.0f;
        g_cnt[0][i] = 0;     g_cnt[1][i] = 0;
    }
}

__global__ void k_halfcpy_b(const float* __restrict__ in0, const float* __restrict__ in1,
                            int n4) {
    int b = blockIdx.y;
    const float* in = b ? in1 : in0;
    __half* out = g_xh[b];
    int i = blockIdx.x * blockDim.x + threadIdx.x;
    if (i < n4) {
        float4 v = ((const float4*)in)[i];
        __half2 h0 = __float22half2_rn(make_float2(v.x, v.y));
        __half2 h1 = __float22half2_rn(make_float2(v.z, v.w));
        ((uint2*)out)[i] = make_uint2(*(uint32_t*)&h0, *(uint32_t*)&h1);
    }
}

// W [L][K][N] f32 -> W^T [L][N][K] half
__global__ void k_halfT_b(const float* __restrict__ in0, const float* __restrict__ in1,
                          int total) {
    int b = blockIdx.y;
    const float* in = b ? in1 : in0;
    __half* out = g_wt[b];
    int idx = blockIdx.x * blockDim.x + threadIdx.x;
    if (idx < total) {
        int l = idx >> 16;
        int rem = idx & 65535;
        int k = rem >> 8, n = rem & 255;
        out[(size_t)l * 65536 + n * 256 + k] = __float2half(in[idx]);
    }
}

__global__ void k_deg_cnt_b(const int* __restrict__ e0, const int* __restrict__ e1,
                            const float* __restrict__ w0, const float* __restrict__ w1) {
    int b = blockIdx.y;
    const int* edges = b ? e1 : e0;
    const float* w = b ? w1 : w0;
    int e = blockIdx.x * blockDim.x + threadIdx.x;
    if (e < E_NUM) {
        int dst = edges[E_NUM + e];
        atomicAdd(&g_dinv[b][dst], w[e]);
        atomicAdd(&g_cnt[b][dst], 1);
    }
}

__global__ void k_scan() {
    int b = blockIdx.x;
    __shared__ int wsum[32];
    __shared__ int chunk_base;
    int tid = threadIdx.x, lane = tid & 31, w = tid >> 5;
    if (tid == 0) chunk_base = 0;
    __syncthreads();
    for (int c0 = 0; c0 < NN_NODE; c0 += 1024) {
        int idx = c0 + tid;
        int v = (idx < NN_NODE) ? g_cnt[b][idx] : 0;
        if (idx < NN_NODE) g_dinv[b][idx] = rsqrtf(g_dinv[b][idx]);
        int sc = v;
        #pragma unroll
        for (int off = 1; off < 32; off <<= 1) {
            int u = __shfl_up_sync(0xffffffffu, sc, off);
            if (lane >= off) sc += u;
        }
        if (lane == 31) wsum[w] = sc;
        __syncthreads();
        if (w == 0) {
            int tv = wsum[lane];
            #pragma unroll
            for (int off = 1; off < 32; off <<= 1) {
                int u = __shfl_up_sync(0xffffffffu, tv, off);
                if (lane >= off) tv += u;
            }
            wsum[lane] = tv;
        }
        __syncthreads();
        int total = wsum[31];
        int excl = chunk_base + (w ? wsum[w - 1] : 0) + sc - v;
        if (idx < NN_NODE) { g_rowptr[b][idx] = excl; g_cnt[b][idx] = 0; }
        __syncthreads();
        if (tid == 0) chunk_base += total;
        __syncthreads();
    }
    if (tid == 0) g_rowptr[b][NN_NODE] = chunk_base;
}

__global__ void k_fill_b(const int* __restrict__ e0, const int* __restrict__ e1,
                         const float* __restrict__ w0, const float* __restrict__ w1) {
    int b = blockIdx.y;
    const int* edges = b ? e1 : e0;
    const float* w = b ? w1 : w0;
    int e = blockIdx.x * blockDim.x + threadIdx.x;
    if (e < E_NUM) {
        int s = edges[e];
        int d = edges[E_NUM + e];
        int pos = g_rowptr[b][d] + atomicAdd(&g_cnt[b][d], 1);
        g_csr_src[b][pos] = s;
        g_csr_norm[b][pos] = g_dinv[b][s] * w[e] * g_dinv[b][d];
    }
}

// ---------------- aggregation: warp-per-node, uint4 gathers, no atomics ----------------
__global__ __launch_bounds__(64) void k_aggregate(const __half* __restrict__ h1, int b,
                                                  const float* __restrict__ bias, int layer) {
    const int w = threadIdx.x >> 5;
    const int l = threadIdx.x & 31;
    const int v = blockIdx.x * 2 + w;
    const uint4* h1v = (const uint4*)h1;

    float dv = g_dinv[b][v];
    float sw = dv * dv;
    uint4 raw = h1v[(size_t)v * 32 + l];
    float acc[8];
    {
        float2 c0 = __half22float2(*(__half2*)&raw.x);
        float2 c1 = __half22float2(*(__half2*)&raw.y);
        float2 c2 = __half22float2(*(__half2*)&raw.z);
        float2 c3 = __half22float2(*(__half2*)&raw.w);
        acc[0] = sw * c0.x; acc[1] = sw * c0.y; acc[2] = sw * c1.x; acc[3] = sw * c1.y;
        acc[4] = sw * c2.x; acc[5] = sw * c2.y; acc[6] = sw * c3.x; acc[7] = sw * c3.y;
    }

    int e = g_rowptr[b][v];
    int e2 = g_rowptr[b][v + 1];
    const int*   srcs  = g_csr_src[b];
    const float* norms = g_csr_norm[b];

    auto fma8 = [&](float n, uint4 r) {
        float2 c0 = __half22float2(*(__half2*)&r.x);
        float2 c1 = __half22float2(*(__half2*)&r.y);
        float2 c2 = __half22float2(*(__half2*)&r.z);
        float2 c3 = __half22float2(*(__half2*)&r.w);
        acc[0] += n * c0.x; acc[1] += n * c0.y; acc[2] += n * c1.x; acc[3] += n * c1.y;
        acc[4] += n * c2.x; acc[5] += n * c2.y; acc[6] += n * c3.x; acc[7] += n * c3.y;
    };

    for (; e + 4 <= e2; e += 4) {
        int u0 = srcs[e], u1 = srcs[e + 1], u2 = srcs[e + 2], u3 = srcs[e + 3];
        float n0 = norms[e], n1 = norms[e + 1], n2 = norms[e + 2], n3 = norms[e + 3];
        uint4 r0 = h1v[(size_t)u0 * 32 + l];
        uint4 r1 = h1v[(size_t)u1 * 32 + l];
        uint4 r2 = h1v[(size_t)u2 * 32 + l];
        uint4 r3 = h1v[(size_t)u3 * 32 + l];
        fma8(n0, r0); fma8(n1, r1); fma8(n2, r2); fma8(n3, r3);
    }
    for (; e < e2; e++) fma8(norms[e], h1v[(size_t)srcs[e] * 32 + l]);

    const float4* bf = (const float4*)bias;
    float4 b0 = bf[l * 2], b1 = bf[l * 2 + 1];
    acc[0] = fmaxf(acc[0] + b0.x, 0.f); acc[1] = fmaxf(acc[1] + b0.y, 0.f);
    acc[2] = fmaxf(acc[2] + b0.z, 0.f); acc[3] = fmaxf(acc[3] + b0.w, 0.f);
    acc[4] = fmaxf(acc[4] + b1.x, 0.f); acc[5] = fmaxf(acc[5] + b1.y, 0.f);
    acc[6] = fmaxf(acc[6] + b1.z, 0.f); acc[7] = fmaxf(acc[7] + b1.w, 0.f);

    __half2 h0 = __float22half2_rn(make_float2(acc[0], acc[1]));
    __half2 h1p = __float22half2_rn(make_float2(acc[2], acc[3]));
    __half2 h2 = __float22half2_rn(make_float2(acc[4], acc[5]));
    __half2 h3 = __float22half2_rn(make_float2(acc[6], acc[7]));
    uint4 outv = make_uint4(*(uint32_t*)&h0, *(uint32_t*)&h1p, *(uint32_t*)&h2, *(uint32_t*)&h3);
    *(uint4*)&g_feats[b][(size_t)v * KTOT + layer * FDIM + l * 8] = outv;

    float m = acc[0];
    #pragma unroll
    for (int q = 1; q < 8; q++) m = fmaxf(m, acc[q]);
    #pragma unroll
    for (int off = 16; off > 0; off >>= 1)
        m = fmaxf(m, __shfl_xor_sync(0xffffffffu, m, off));
    if (l == 0) g_nodemax[b][layer][v] = m;
}

// ---------------- attention FC (with node-max reduction) + effective conv weights ----------------
__global__ void k_attfc2(const float* __restrict__ fc1w, const float* __restrict__ fc1b,
                         const float* __restrict__ fc2w, const float* __restrict__ fc2b, int b) {
    __shared__ float red[256];
    __shared__ float amax_s[NLAYERS];
    int tid = threadIdx.x;
    for (int c = 0; c < NLAYERS; c++) {
        float m = 0.f;
        for (int i = tid; i < NN_NODE; i += 256) m = fmaxf(m, g_nodemax[b][c][i]);
        red[tid] = m;
        __syncthreads();
        for (int o = 128; o > 0; o >>= 1) {
            if (tid < o) red[tid] = fmaxf(red[tid], red[tid + o]);
            __syncthreads();
        }
        if (tid == 0) amax_s[c] = red[0];
        __syncthreads();
    }
    if (tid == 0) {
        float t[5 * NLAYERS];
        for (int j = 0; j < 5 * NLAYERS; j++) {
            float s = fc1b[j];
            for (int c = 0; c < NLAYERS; c++) s += fc1w[j * NLAYERS + c] * amax_s[c];
            t[j] = fmaxf(s, 0.f);
        }
        for (int c = 0; c < NLAYERS; c++) {
            float s = fc2b[c];
            for (int j = 0; j < 5 * NLAYERS; j++) s += fc2w[c * (5 * NLAYERS) + j] * t[j];
            g_atts[b][c] = 1.0f / (1.0f + expf(-s));
        }
    }
}

__global__ void k_weff(const float* __restrict__ cw, int b) {
    int idx = blockIdx.x * blockDim.x + threadIdx.x;
    if (idx < OC * KTOT) {
        int c = (idx % KTOT) >> 8;
        g_weff[b][idx] = __float2half(cw[idx] * g_atts[b][c]);
    }
}

// ---------------- launch ----------------
extern "C" void kernel_launch(void* const* d_in, const int* in_sizes, int n_in,
                              void* d_out, int out_size) {
    const float* x_m    = (const float*)d_in[0];
    const float* x_d    = (const float*)d_in[1];
    const float* w_m    = (const float*)d_in[2];
    const float* w_d    = (const float*)d_in[3];
    const float* Wx     = (const float*)d_in[4];
    const float* bx     = (const float*)d_in[5];
    const float* Wy     = (const float*)d_in[6];
    const float* by     = (const float*)d_in[7];
    const float* fc1x_w = (const float*)d_in[8];
    const float* fc1x_b = (const float*)d_in[9];
    const float* fc2x_w = (const float*)d_in[10];
    const float* fc2x_b = (const float*)d_in[11];
    const float* fc1y_w = (const float*)d_in[12];
    const float* fc1y_b = (const float*)d_in[13];
    const float* fc2y_w = (const float*)d_in[14];
    const float* fc2y_b = (const float*)d_in[15];
    const float* cnnx_w = (const float*)d_in[16];
    const float* cnnx_b = (const float*)d_in[17];
    const float* cnny_w = (const float*)d_in[18];
    const float* cnny_b = (const float*)d_in[19];
    const int*   edges_m = (const int*)d_in[20];
    const int*   edges_d = (const int*)d_in[21];
    float* out = (float*)d_out;

    __half *p_h1, *p_feats, *p_weff, *p_emb, *p_xh, *p_wt;
    cudaGetSymbolAddress((void**)&p_h1,    g_h1);
    cudaGetSymbolAddress((void**)&p_feats, g_feats);
    cudaGetSymbolAddress((void**)&p_weff,  g_weff);
    cudaGetSymbolAddress((void**)&p_emb,   g_emb);
    cudaGetSymbolAddress((void**)&p_xh,    g_xh);
    cudaGetSymbolAddress((void**)&p_wt,    g_wt);

    __half* emb0 = p_emb;
    __half* emb1 = p_emb + (size_t)NN_NODE * OC;

    const int MT = (NN_NODE + 127) / 128;   // 79
    const int SM_F16 = 3 * (128 * 20 + 128 * 20) * 4;  // 61440

    cudaEventRecord(g_hx.ev_fork, 0);
    cudaStreamWaitEvent(g_hx.s0, g_hx.ev_fork, 0);
    cudaStreamWaitEvent(g_hx.s1, g_hx.ev_fork, 0);

    // s0: conversions (needed by GEMM0 of both branches)
    k_halfcpy_b<<<dim3((NN_NODE * FDIM / 4 + 255) / 256, 2), 256, 0, g_hx.s0>>>(x_m, x_d, NN_NODE * FDIM / 4);
    k_halfT_b<<<dim3((NLAYERS * FDIM * FDIM + 255) / 256, 2), 256, 0, g_hx.s0>>>(Wx, Wy, NLAYERS * FDIM * FDIM);
    cudaEventRecord(g_hx.ev_h, g_hx.s0);

    // s1: CSR build (needed only by aggregates)
    k_init<<<(NN_NODE + 255) / 256, 256, 0, g_hx.s1>>>();
    k_deg_cnt_b<<<dim3(E_NUM / 256, 2), 256, 0, g_hx.s1>>>(edges_m, edges_d, w_m, w_d);
    k_scan<<<2, 1024, 0, g_hx.s1>>>();
    k_fill_b<<<dim3(E_NUM / 256, 2), 256, 0, g_hx.s1>>>(edges_m, edges_d, w_m, w_d);
    cudaEventRecord(g_hx.ev_csr, g_hx.s1);

    // cross deps: s1's GEMM0 needs conversions; s0's first aggregate needs CSR
    cudaStreamWaitEvent(g_hx.s1, g_hx.ev_h, 0);

    for (int b = 0; b < 2; b++) {
        cudaStream_t st = b ? g_hx.s1 : g_hx.s0;
        const float* bias  = b ? by : bx;
        const float* fc1w  = b ? fc1y_w : fc1x_w;
        const float* fc1b  = b ? fc1y_b : fc1x_b;
        const float* fc2w  = b ? fc2y_w : fc2x_w;
        const float* fc2b  = b ? fc2y_b : fc2x_b;
        const float* cw    = b ? cnny_w : cnnx_w;
        const float* cb    = b ? cnny_b : cnnx_b;
        __half* featsB = p_feats + (size_t)b * NN_NODE * KTOT;
        __half* h1B    = p_h1    + (size_t)b * NN_NODE * FDIM;
        __half* xhB    = p_xh    + (size_t)b * NN_NODE * FDIM;
        __half* wtB    = p_wt    + (size_t)b * NLAYERS * FDIM * FDIM;
        __half* weffB  = p_weff  + (size_t)b * OC * KTOT;
        __half* embB   = b ? emb1 : emb0;

        const __half* hin = xhB;
        int lda = FDIM;
        for (int i = 0; i < NLAYERS; i++) {
            // anti-phase: b1's GEMM(i) starts only after b0's GEMM(i) completes,
            // so agg(b0,i) overlaps GEMM(b1,i) and aggs never co-run on L2.
            if (b == 1) cudaStreamWaitEvent(g_hx.s1, g_hx.ev_gl[i], 0);
            k_gemm_f16<0, 1, 0><<<dim3(FDIM / 128, MT), 256, SM_F16, st>>>(
                NN_NODE, FDIM, FDIM,
                hin, hin, lda,
                wtB + (size_t)i * FDIM * FDIM, wtB + (size_t)i * FDIM * FDIM, FDIM,
                h1B, h1B, FDIM, nullptr, nullptr);
            if (b == 0) cudaEventRecord(g_hx.ev_gl[i], g_hx.s0);
            if (b == 0 && i == 0) cudaStreamWaitEvent(g_hx.s0, g_hx.ev_csr, 0);
            k_aggregate<<<NN_NODE / 2, 64, 0, st>>>(h1B, b, bias + (size_t)i * FDIM, i);
            hin = featsB + (size_t)i * FDIM;
            lda = KTOT;
        }

        // per-branch tail starts as soon as this branch's layers finish
        k_attfc2<<<1, 256, 0, st>>>(fc1w, fc1b, fc2w, fc2b, b);
        k_weff<<<(OC * KTOT + 255) / 256, 256, 0, st>>>(cw, b);
        k_gemm_f16<1, 1, 0><<<dim3(1, MT, 1), 256, SM_F16, st>>>(
            NN_NODE, OC, KTOT,
            featsB, featsB, KTOT,
            weffB, weffB, KTOT,
            embB, embB, OC,
            cb, cb);
    }

    cudaEventRecord(g_hx.ev_j0, g_hx.s0);
    cudaEventRecord(g_hx.ev_j1, g_hx.s1);
    cudaStreamWaitEvent(0, g_hx.ev_j0, 0);
    cudaStreamWaitEvent(0, g_hx.ev_j1, 0);

    k_gemm_f16<0, 0, 1><<<dim3(MT, MT, 1), 256, SM_F16>>>(
        NN_NODE, NN_NODE, OC,
        emb0, emb0, OC,
        emb1, emb1, OC,
        out, out, NN_NODE,
        nullptr, nullptr);
}